// round 14
// baseline (speedup 1.0000x reference)
#include <cuda_runtime.h>
#include <cuda_bf16.h>
#include <math.h>
#include <stdint.h>

#define NN 16384
#define NE 65536
typedef __nv_bfloat16 bf16;

// ---------------- fp32 scratch ----------------
static __device__ __align__(256) float g_U[128 * 128];
static __device__ __align__(256) float g_V[128 * 128];
static __device__ __align__(256) float g_NR[NN * 384];
static __device__ __align__(256) float g_mix[10][NN * 128];
static __device__ __align__(256) float g_Wt[32 * 384];
static __device__ __align__(256) float g_db[384];
static __device__ __align__(256) float g_edp[(size_t)NE * 384];
static __device__ int g_Etot;

// ---------------- bf16 hi/lo activations ----------------
static __device__ __align__(256) bf16 g_accH[10 * NN * 128], g_accL[10 * NN * 128];
static __device__ __align__(256) bf16 g_TH[NN * 128],  g_TL[NN * 128];
static __device__ __align__(256) bf16 g_H1H[NN * 256], g_H1L[NN * 256];
static __device__ __align__(256) bf16 g_XNH[NN * 384], g_XNL[NN * 384];

// ---------------- bf16 hi/lo weights ----------------
static __device__ __align__(256) bf16 w_ls0H[256 * 128], w_ls0L[256 * 128];
static __device__ __align__(256) bf16 w_ls1H[384 * 256], w_ls1L[384 * 256];
static __device__ __align__(256) bf16 w_linH[128 * 384], w_linL[128 * 384];
static __device__ __align__(256) bf16 w_ltH[3 * 128 * 128], w_ltL[3 * 128 * 128];
static __device__ __align__(256) bf16 w_ol1H[64 * 128], w_ol1L[64 * 128];

// ---------------- CSR edge compaction ----------------
static __device__ __align__(256) int    g_cnt[NN];
static __device__ __align__(256) int    g_off[NN];
static __device__ __align__(256) int    g_fill[NN];
static __device__ __align__(256) float4 g_erec[NE];
static __device__ __align__(256) int    g_ez[NE];

__device__ __forceinline__ float silu(float x) { return x / (1.f + expf(-x)); }
__device__ __forceinline__ void split1(float v, bf16& h, bf16& l) {
    h = __float2bfloat16(v);
    l = __float2bfloat16(v - __bfloat162float(h));
}

#define RBF_START 0.011108996538242306
#define RBF_BETA  (1.0 / ((0.0625 * (1.0 - RBF_START)) * (0.0625 * (1.0 - RBF_START))))
#define RBF_ALPHA (5.0 / 4.5)
#define PI_OVER_C 0.6981317007977318

// =================== MMA plumbing ===================
__device__ __forceinline__ uint32_t smem_u32(const void* p) {
    uint32_t a;
    asm("{ .reg .u64 t; cvta.to.shared.u64 t, %1; cvt.u32.u64 %0, t; }" : "=r"(a) : "l"(p));
    return a;
}
__device__ __forceinline__ void ldm_x4(uint32_t addr, uint32_t* r) {
    asm volatile("ldmatrix.sync.aligned.m8n8.x4.shared.b16 {%0,%1,%2,%3}, [%4];"
                 : "=r"(r[0]), "=r"(r[1]), "=r"(r[2]), "=r"(r[3]) : "r"(addr));
}
__device__ __forceinline__ void mma16816(float* c, const uint32_t* a, const uint32_t* b) {
    asm volatile("mma.sync.aligned.m16n8k16.row.col.f32.bf16.bf16.f32 "
                 "{%0,%1,%2,%3}, {%4,%5,%6,%7}, {%8,%9}, {%0,%1,%2,%3};"
                 : "+f"(c[0]), "+f"(c[1]), "+f"(c[2]), "+f"(c[3])
                 : "r"(a[0]), "r"(a[1]), "r"(a[2]), "r"(a[3]), "r"(b[0]), "r"(b[1]));
}
__device__ __forceinline__ void cpa16(uint32_t s, const void* g) {
    asm volatile("cp.async.cg.shared.global [%0], [%1], 16;" :: "r"(s), "l"(g));
}
#define CP_COMMIT() asm volatile("cp.async.commit_group;")
#define CP_WAIT0()  asm volatile("cp.async.wait_group 0;" ::: "memory")

#define TPAD 136
#define SM_A (128 * TPAD * 2)
#define SM_W (64 * TPAD * 2)
#define TG_SMEM (2 * SM_A + 2 * SM_W)   // 104448 -> 2 CTAs/SM

template <int OUT, int FT>
__device__ __forceinline__ void mma_gemm_bf(
    int bx, int by,
    const bf16* __restrict__ AH, const bf16* __restrict__ AL,
    const bf16* __restrict__ WH, const bf16* __restrict__ WL,
    const float* __restrict__ bias,
    float* __restrict__ C, bf16* __restrict__ CH, bf16* __restrict__ CL,
    int K, int F, bool act) {
    extern __shared__ __align__(16) char smem[];
    const uint32_t aH_u = smem_u32(smem);
    const uint32_t aL_u = aH_u + SM_A;
    const uint32_t wH_u = aH_u + 2 * SM_A;
    const uint32_t wL_u = wH_u + SM_W;

    const int tid = threadIdx.x, lane = tid & 31, wid = tid >> 5;
    const int wm = wid & 3, wn = wid >> 2;
    const int m0 = bx << 7;
    const int f0 = by * (64 * FT);

    float c[FT][2][4][4];
    #pragma unroll
    for (int ft = 0; ft < FT; ft++)
        #pragma unroll
        for (int i = 0; i < 2; i++)
            #pragma unroll
            for (int j = 0; j < 4; j++)
                #pragma unroll
                for (int q = 0; q < 4; q++) c[ft][i][j][q] = 0.f;

    const int a_row = wm * 32 + (lane & 15);
    const int a_col = (lane >> 4) << 3;
    const int b_row = wn * 32 + (lane & 7) + ((lane >> 4) << 3);
    const int b_col = ((lane >> 3) & 1) << 3;

    for (int kc = 0; kc < K; kc += 128) {
        __syncthreads();
        #pragma unroll
        for (int i = tid; i < 2048; i += 256) {
            int r = i >> 4, c8 = (i & 15) << 3;
            uint32_t so = (uint32_t)(r * TPAD + c8) * 2;
            size_t go = (size_t)(m0 + r) * K + kc + c8;
            cpa16(aH_u + so, AH + go);
            cpa16(aL_u + so, AL + go);
        }
        #pragma unroll
        for (int i = tid; i < 1024; i += 256) {
            int r = i >> 4, c8 = (i & 15) << 3;
            uint32_t so = (uint32_t)(r * TPAD + c8) * 2;
            size_t go = (size_t)(f0 + r) * K + kc + c8;
            cpa16(wH_u + so, WH + go);
            cpa16(wL_u + so, WL + go);
        }
        CP_COMMIT();
        CP_WAIT0();
        __syncthreads();

        #pragma unroll
        for (int ft = 0; ft < FT; ft++) {
            if (ft > 0) {
                __syncthreads();
                #pragma unroll
                for (int i = tid; i < 1024; i += 256) {
                    int r = i >> 4, c8 = (i & 15) << 3;
                    uint32_t so = (uint32_t)(r * TPAD + c8) * 2;
                    size_t go = (size_t)(f0 + ft * 64 + r) * K + kc + c8;
                    cpa16(wH_u + so, WH + go);
                    cpa16(wL_u + so, WL + go);
                }
                CP_COMMIT();
                CP_WAIT0();
                __syncthreads();
            }
            #pragma unroll
            for (int ks = 0; ks < 8; ks++) {
                uint32_t ah[2][4], al[2][4];
                #pragma unroll
                for (int mf = 0; mf < 2; mf++) {
                    uint32_t off = (uint32_t)((a_row + mf * 16) * TPAD + a_col + ks * 16) * 2;
                    ldm_x4(aH_u + off, ah[mf]);
                    ldm_x4(aL_u + off, al[mf]);
                }
                #pragma unroll
                for (int nfp = 0; nfp < 2; nfp++) {
                    uint32_t boff = (uint32_t)((b_row + nfp * 16) * TPAD + b_col + ks * 16) * 2;
                    uint32_t bh[4], bl[4];
                    ldm_x4(wH_u + boff, bh);
                    ldm_x4(wL_u + boff, bl);
                    #pragma unroll
                    for (int mf = 0; mf < 2; mf++) {
                        mma16816(c[ft][mf][2 * nfp], ah[mf], bh);
                        mma16816(c[ft][mf][2 * nfp], ah[mf], bl);
                        mma16816(c[ft][mf][2 * nfp], al[mf], bh);
                        mma16816(c[ft][mf][2 * nfp + 1], ah[mf], bh + 2);
                        mma16816(c[ft][mf][2 * nfp + 1], ah[mf], bl + 2);
                        mma16816(c[ft][mf][2 * nfp + 1], al[mf], bh + 2);
                    }
                }
            }
        }
    }

    #pragma unroll
    for (int ft = 0; ft < FT; ft++) {
        #pragma unroll
        for (int mf = 0; mf < 2; mf++) {
            #pragma unroll
            for (int nf = 0; nf < 4; nf++) {
                int grow = m0 + wm * 32 + mf * 16 + (lane >> 2);
                int gcol = f0 + ft * 64 + wn * 32 + nf * 8 + ((lane & 3) << 1);
                float b0 = bias ? bias[gcol] : 0.f;
                float b1 = bias ? bias[gcol + 1] : 0.f;
                float v0 = c[ft][mf][nf][0] + b0, v1 = c[ft][mf][nf][1] + b1;
                float v2 = c[ft][mf][nf][2] + b0, v3 = c[ft][mf][nf][3] + b1;
                if (act) { v0 = silu(v0); v1 = silu(v1); v2 = silu(v2); v3 = silu(v3); }
                if (OUT == 0) {
                    *(float2*)&C[(size_t)grow * F + gcol] = make_float2(v0, v1);
                    *(float2*)&C[(size_t)(grow + 8) * F + gcol] = make_float2(v2, v3);
                } else {
                    bf16 h0, l0, h1, l1;
                    split1(v0, h0, l0); split1(v1, h1, l1);
                    *(__nv_bfloat162*)&CH[(size_t)grow * F + gcol] = __halves2bfloat162(h0, h1);
                    *(__nv_bfloat162*)&CL[(size_t)grow * F + gcol] = __halves2bfloat162(l0, l1);
                    split1(v2, h0, l0); split1(v3, h1, l1);
                    *(__nv_bfloat162*)&CH[(size_t)(grow + 8) * F + gcol] = __halves2bfloat162(h0, h1);
                    *(__nv_bfloat162*)&CL[(size_t)(grow + 8) * F + gcol] = __halves2bfloat162(l0, l1);
                }
            }
        }
    }
}

__global__ __launch_bounds__(256, 2)
void tg_mixls0(const float* __restrict__ ls0b) {
    int bid = blockIdx.x;
    if (bid < 1280) {
        int plane = bid >> 7;
        int sel = (plane == 0) ? 0 : (plane < 4 ? 1 : 2);
        mma_gemm_bf<0, 2>(bid, 0, g_accH, g_accL, w_ltH + sel * 16384, w_ltL + sel * 16384,
                          nullptr, &g_mix[0][0], nullptr, nullptr, 128, 128, false);
    } else {
        int b = bid - 1280;
        mma_gemm_bf<1, 2>(b & 127, b >> 7, g_TH, g_TL, w_ls0H, w_ls0L, ls0b,
                          nullptr, g_H1H, g_H1L, 128, 256, true);
    }
}
__global__ __launch_bounds__(256, 2)
void tg_ls1(const float* __restrict__ b) {
    mma_gemm_bf<0, 2>(blockIdx.x, blockIdx.y, g_H1H, g_H1L, w_ls1H, w_ls1L, b,
                      g_NR, nullptr, nullptr, 256, 384, true);
}

// =================== fused tail: combine+LN(384) -> lin -> ol1 -> final dot =============
__global__ __launch_bounds__(256, 2)
void tg_tail(const float* __restrict__ ong, const float* __restrict__ onb,
             const float* __restrict__ linb, const float* __restrict__ ol1b,
             const float* __restrict__ ol2w, const float* __restrict__ ol2b,
             float* __restrict__ y) {
    extern __shared__ __align__(16) char smem[];
    const uint32_t aH_u = smem_u32(smem);
    const uint32_t aL_u = aH_u + SM_A;
    const uint32_t wH_u = aH_u + 2 * SM_A;
    const uint32_t wL_u = wH_u + SM_W;
    __shared__ float ypart[128];

    const int tid = threadIdx.x, lane = tid & 31, wid = tid >> 5;
    const int wm = wid & 3, wn = wid >> 2;
    const int m0 = blockIdx.x << 7;

    // ---------- phase 0: combine + layernorm(384) for this block's 128 nodes ----------
    for (int n_l = wid; n_l < 128; n_l += 8) {
        int n = m0 + n_l;
        size_t base = (size_t)n << 7;
        float xs[3][4];
        #pragma unroll
        for (int q = 0; q < 4; q++) {
            int k = lane + q * 32;
            size_t idx = base + k;
            float Ip = g_mix[0][idx];
            float B0 = g_mix[1][idx], B1 = g_mix[2][idx], B2 = g_mix[3][idx];
            float xx = g_mix[4][idx], yy = g_mix[5][idx], zz = g_mix[6][idx];
            float xy = g_mix[7][idx], xz = g_mix[8][idx], yz = g_mix[9][idx];
            const float* nr = &g_NR[(size_t)n * 384 + 3 * k];
            float n0 = nr[0], n1 = nr[1], n2 = nr[2];
            float t = Ip * n0;
            xs[0][q] = 3.f * t * t;
            float bb = B0 * B0 + B1 * B1 + B2 * B2;
            xs[1][q] = 2.f * bb * n1 * n1;
            float tr = xx + yy + zz;
            float ms = xx * xx + yy * yy + zz * zz + 2.f * (xy * xy + xz * xz + yz * yz);
            xs[2][q] = (ms - tr * tr * (1.f / 3.f)) * n2 * n2;
        }
        float s = 0.f;
        #pragma unroll
        for (int cc = 0; cc < 3; cc++)
            #pragma unroll
            for (int q = 0; q < 4; q++) s += xs[cc][q];
        #pragma unroll
        for (int o = 16; o; o >>= 1) s += __shfl_xor_sync(0xffffffffu, s, o);
        float mean = s * (1.f / 384.f);
        float v = 0.f;
        #pragma unroll
        for (int cc = 0; cc < 3; cc++)
            #pragma unroll
            for (int q = 0; q < 4; q++) {
                float dv = xs[cc][q] - mean;
                v += dv * dv;
            }
        #pragma unroll
        for (int o = 16; o; o >>= 1) v += __shfl_xor_sync(0xffffffffu, v, o);
        float rs = rsqrtf(v * (1.f / 384.f) + 1e-5f);
        #pragma unroll
        for (int cc = 0; cc < 3; cc++)
            #pragma unroll
            for (int q = 0; q < 4; q++) {
                int gi = cc * 128 + lane + q * 32;
                float o = (xs[cc][q] - mean) * rs * ong[gi] + onb[gi];
                bf16 hh, ll;
                split1(o, hh, ll);
                g_XNH[(size_t)n * 384 + gi] = hh;
                g_XNL[(size_t)n * 384 + gi] = ll;
            }
    }
    __syncthreads();   // block's XN writes visible to block's cp.async reads

    const int a_row = wm * 32 + (lane & 15);
    const int a_col = (lane >> 4) << 3;
    const int b_row = wn * 32 + (lane & 7) + ((lane >> 4) << 3);
    const int b_col = ((lane >> 3) & 1) << 3;

    // ---------- phase 1: lin GEMM (K=384, F=128, FT=2) ----------
    float c[2][2][4][4];
    #pragma unroll
    for (int ft = 0; ft < 2; ft++)
        #pragma unroll
        for (int i = 0; i < 2; i++)
            #pragma unroll
            for (int j = 0; j < 4; j++)
                #pragma unroll
                for (int q = 0; q < 4; q++) c[ft][i][j][q] = 0.f;

    for (int kc = 0; kc < 384; kc += 128) {
        __syncthreads();
        #pragma unroll
        for (int i = tid; i < 2048; i += 256) {
            int r = i >> 4, c8 = (i & 15) << 3;
            uint32_t so = (uint32_t)(r * TPAD + c8) * 2;
            size_t go = (size_t)(m0 + r) * 384 + kc + c8;
            cpa16(aH_u + so, g_XNH + go);
            cpa16(aL_u + so, g_XNL + go);
        }
        #pragma unroll
        for (int i = tid; i < 1024; i += 256) {
            int r = i >> 4, c8 = (i & 15) << 3;
            uint32_t so = (uint32_t)(r * TPAD + c8) * 2;
            size_t go = (size_t)r * 384 + kc + c8;
            cpa16(wH_u + so, w_linH + go);
            cpa16(wL_u + so, w_linL + go);
        }
        CP_COMMIT();
        CP_WAIT0();
        __syncthreads();

        #pragma unroll
        for (int ft = 0; ft < 2; ft++) {
            if (ft > 0) {
                __syncthreads();
                #pragma unroll
                for (int i = tid; i < 1024; i += 256) {
                    int r = i >> 4, c8 = (i & 15) << 3;
                    uint32_t so = (uint32_t)(r * TPAD + c8) * 2;
                    size_t go = (size_t)(64 + r) * 384 + kc + c8;
                    cpa16(wH_u + so, w_linH + go);
                    cpa16(wL_u + so, w_linL + go);
                }
                CP_COMMIT();
                CP_WAIT0();
                __syncthreads();
            }
            #pragma unroll
            for (int ks = 0; ks < 8; ks++) {
                uint32_t ah[2][4], al[2][4];
                #pragma unroll
                for (int mf = 0; mf < 2; mf++) {
                    uint32_t off = (uint32_t)((a_row + mf * 16) * TPAD + a_col + ks * 16) * 2;
                    ldm_x4(aH_u + off, ah[mf]);
                    ldm_x4(aL_u + off, al[mf]);
                }
                #pragma unroll
                for (int nfp = 0; nfp < 2; nfp++) {
                    uint32_t boff = (uint32_t)((b_row + nfp * 16) * TPAD + b_col + ks * 16) * 2;
                    uint32_t bh[4], bl[4];
                    ldm_x4(wH_u + boff, bh);
                    ldm_x4(wL_u + boff, bl);
                    #pragma unroll
                    for (int mf = 0; mf < 2; mf++) {
                        mma16816(c[ft][mf][2 * nfp], ah[mf], bh);
                        mma16816(c[ft][mf][2 * nfp], ah[mf], bl);
                        mma16816(c[ft][mf][2 * nfp], al[mf], bh);
                        mma16816(c[ft][mf][2 * nfp + 1], ah[mf], bh + 2);
                        mma16816(c[ft][mf][2 * nfp + 1], ah[mf], bl + 2);
                        mma16816(c[ft][mf][2 * nfp + 1], al[mf], bh + 2);
                    }
                }
            }
        }
    }

    // ---------- stage G1 (silu'd, hi/lo) into A region; fill ol1 weights ----------
    __syncthreads();
    #pragma unroll
    for (int ft = 0; ft < 2; ft++) {
        #pragma unroll
        for (int mf = 0; mf < 2; mf++) {
            #pragma unroll
            for (int nf = 0; nf < 4; nf++) {
                int lrow = wm * 32 + mf * 16 + (lane >> 2);
                int lcol = ft * 64 + wn * 32 + nf * 8 + ((lane & 3) << 1);
                float b0 = linb[lcol], b1 = linb[lcol + 1];
                float v0 = silu(c[ft][mf][nf][0] + b0);
                float v1 = silu(c[ft][mf][nf][1] + b1);
                float v2 = silu(c[ft][mf][nf][2] + b0);
                float v3 = silu(c[ft][mf][nf][3] + b1);
                bf16 h0, l0, h1, l1;
                split1(v0, h0, l0); split1(v1, h1, l1);
                *(__nv_bfloat162*)(smem + (size_t)(lrow * TPAD + lcol) * 2) =
                    __halves2bfloat162(h0, h1);
                *(__nv_bfloat162*)(smem + SM_A + (size_t)(lrow * TPAD + lcol) * 2) =
                    __halves2bfloat162(l0, l1);
                split1(v2, h0, l0); split1(v3, h1, l1);
                *(__nv_bfloat162*)(smem + (size_t)((lrow + 8) * TPAD + lcol) * 2) =
                    __halves2bfloat162(h0, h1);
                *(__nv_bfloat162*)(smem + SM_A + (size_t)((lrow + 8) * TPAD + lcol) * 2) =
                    __halves2bfloat162(l0, l1);
            }
        }
    }
    #pragma unroll
    for (int i = tid; i < 1024; i += 256) {
        int r = i >> 4, c8 = (i & 15) << 3;
        if (r < 64) {
            uint32_t so = (uint32_t)(r * TPAD + c8) * 2;
            cpa16(wH_u + so, w_ol1H + r * 128 + c8);
            cpa16(wL_u + so, w_ol1L + r * 128 + c8);
        }
    }
    CP_COMMIT();
    CP_WAIT0();
    if (tid < 128) ypart[tid] = 0.f;
    __syncthreads();

    // ---------- phase 2: ol1 GEMM (K=128, F=64) + final dot ----------
    float c2[2][4][4];
    #pragma unroll
    for (int i = 0; i < 2; i++)
        #pragma unroll
        for (int j = 0; j < 4; j++)
            #pragma unroll
            for (int q = 0; q < 4; q++) c2[i][j][q] = 0.f;

    #pragma unroll
    for (int ks = 0; ks < 8; ks++) {
        uint32_t ah[2][4], al[2][4];
        #pragma unroll
        for (int mf = 0; mf < 2; mf++) {
            uint32_t off = (uint32_t)((a_row + mf * 16) * TPAD + a_col + ks * 16) * 2;
            ldm_x4(aH_u + off, ah[mf]);
            ldm_x4(aL_u + off, al[mf]);
        }
        #pragma unroll
        for (int nfp = 0; nfp < 2; nfp++) {
            uint32_t boff = (uint32_t)((b_row + nfp * 16) * TPAD + b_col + ks * 16) * 2;
            uint32_t bh[4], bl[4];
            ldm_x4(wH_u + boff, bh);
            ldm_x4(wL_u + boff, bl);
            #pragma unroll
            for (int mf = 0; mf < 2; mf++) {
                mma16816(c2[mf][2 * nfp], ah[mf], bh);
                mma16816(c2[mf][2 * nfp], ah[mf], bl);
                mma16816(c2[mf][2 * nfp], al[mf], bh);
                mma16816(c2[mf][2 * nfp + 1], ah[mf], bh + 2);
                mma16816(c2[mf][2 * nfp + 1], ah[mf], bl + 2);
                mma16816(c2[mf][2 * nfp + 1], al[mf], bh + 2);
            }
        }
    }

    #pragma unroll
    for (int mf = 0; mf < 2; mf++) {
        float pr0 = 0.f, pr8 = 0.f;
        #pragma unroll
        for (int nf = 0; nf < 4; nf++) {
            int gcol = wn * 32 + nf * 8 + ((lane & 3) << 1);
            float b0 = ol1b[gcol], b1 = ol1b[gcol + 1];
            float w0 = ol2w[gcol], w1 = ol2w[gcol + 1];
            pr0 += silu(c2[mf][nf][0] + b0) * w0 + silu(c2[mf][nf][1] + b1) * w1;
            pr8 += silu(c2[mf][nf][2] + b0) * w0 + silu(c2[mf][nf][3] + b1) * w1;
        }
        int lrow = wm * 32 + mf * 16 + (lane >> 2);
        atomicAdd(&ypart[lrow], pr0);
        atomicAdd(&ypart[lrow + 8], pr8);
    }
    __syncthreads();
    if (tid < 128) y[m0 + tid] = ypart[tid] + ol2b[0];
}

// =================== launch #1: edge count + U/V + dp transpose + weight split =========
__global__ void k_count(const int* __restrict__ ei, const float* __restrict__ pos,
                        const float* __restrict__ emb_w, const float* __restrict__ emb2_w,
                        const float* __restrict__ emb2_b,
                        const float* __restrict__ dp1w, const float* __restrict__ dp1b,
                        const float* __restrict__ dp2w, const float* __restrict__ dp2b,
                        const float* __restrict__ dp3w, const float* __restrict__ dp3b,
                        const float* __restrict__ ls0w, const float* __restrict__ ls1w,
                        const float* __restrict__ linw, const float* __restrict__ lt0w,
                        const float* __restrict__ lt1w, const float* __restrict__ lt2w,
                        const float* __restrict__ ol1w) {
    int b = blockIdx.x;
    if (b < 256) {
        int e = b * 256 + threadIdx.x;
        int src = ei[e], dst = ei[NE + e];
        float vx = pos[src * 3 + 0] - pos[dst * 3 + 0];
        float vy = pos[src * 3 + 1] - pos[dst * 3 + 1];
        float vz = pos[src * 3 + 2] - pos[dst * 3 + 2];
        float d = sqrtf(vx * vx + vy * vy + vz * vz);
        if (src == dst || d < 4.5f) atomicAdd(&g_cnt[src], 1);
    } else if (b < 320) {
        int zt = ((b - 256) << 1) | (threadIdx.x >> 7);
        int h = threadIdx.x & 127;
        float u = emb2_b[h];
        float v = 0.f;
        #pragma unroll 4
        for (int k = 0; k < 128; k++) {
            float e = emb_w[zt * 128 + k];
            u = fmaf(e, emb2_w[h * 256 + k], u);
            v = fmaf(e, emb2_w[h * 256 + 128 + k], v);
        }
        g_U[zt * 128 + h] = u;
        g_V[zt * 128 + h] = v;
    } else if (b < 368) {
        int j = (b - 320) * 256 + threadIdx.x;   // 0..12287
        int r = j / 384, col = j - r * 384;
        float v = col < 128 ? dp1w[col * 32 + r]
                : col < 256 ? dp2w[(col - 128) * 32 + r]
                            : dp3w[(col - 256) * 32 + r];
        g_Wt[j] = v;
        if (j < 384)
            g_db[j] = j < 128 ? dp1b[j] : j < 256 ? dp2b[j - 128] : dp3b[j - 256];
    } else {
        int j = (b - 368) * 256 + threadIdx.x;
        const float* src; bf16 *dh, *dl;
        if (j < 32768) { src = ls0w; dh = w_ls0H; dl = w_ls0L; }
        else if ((j -= 32768) < 98304) { src = ls1w; dh = w_ls1H; dl = w_ls1L; }
        else if ((j -= 98304) < 49152) { src = linw; dh = w_linH; dl = w_linL; }
        else if ((j -= 49152) < 16384) { src = lt0w; dh = w_ltH; dl = w_ltL; }
        else if ((j -= 16384) < 16384) { src = lt1w; dh = w_ltH + 16384; dl = w_ltL + 16384; }
        else if ((j -= 16384) < 16384) { src = lt2w; dh = w_ltH + 32768; dl = w_ltL + 32768; }
        else if ((j -= 16384) < 8192)  { src = ol1w; dh = w_ol1H; dl = w_ol1L; }
        else return;
        bf16 h, l;
        split1(src[j], h, l);
        dh[j] = h; dl[j] = l;
    }
}

// launch #2: exclusive scan + total edge count
__global__ void k_scan() {
    __shared__ int ws[32];
    int t = threadIdx.x;
    int lane = t & 31, w = t >> 5;
    int base = t * 16;
    int4 v0 = *(int4*)&g_cnt[base];
    int4 v1 = *(int4*)&g_cnt[base + 4];
    int4 v2 = *(int4*)&g_cnt[base + 8];
    int4 v3 = *(int4*)&g_cnt[base + 12];
    int cv[16] = {v0.x, v0.y, v0.z, v0.w, v1.x, v1.y, v1.z, v1.w,
                  v2.x, v2.y, v2.z, v2.w, v3.x, v3.y, v3.z, v3.w};
    int local[16];
    int s = 0;
    #pragma unroll
    for (int i = 0; i < 16; i++) { local[i] = s; s += cv[i]; }
    int inc = s;
    #pragma unroll
    for (int off = 1; off < 32; off <<= 1) {
        int x = __shfl_up_sync(0xffffffffu, inc, off);
        if (lane >= off) inc += x;
    }
    if (lane == 31) ws[w] = inc;
    __syncthreads();
    if (w == 0) {
        int wi = ws[lane];
        #pragma unroll
        for (int off = 1; off < 32; off <<= 1) {
            int x = __shfl_up_sync(0xffffffffu, wi, off);
            if (lane >= off) wi += x;
        }
        ws[lane] = wi;
    }
    __syncthreads();
    int warp_pre = (w == 0) ? 0 : ws[w - 1];
    int pre = warp_pre + inc - s;
    int4 o0 = make_int4(pre + local[0], pre + local[1], pre + local[2], pre + local[3]);
    int4 o1 = make_int4(pre + local[4], pre + local[5], pre + local[6], pre + local[7]);
    int4 o2 = make_int4(pre + local[8], pre + local[9], pre + local[10], pre + local[11]);
    int4 o3 = make_int4(pre + local[12], pre + local[13], pre + local[14], pre + local[15]);
    *(int4*)&g_off[base] = o0;
    *(int4*)&g_off[base + 4] = o1;
    *(int4*)&g_off[base + 8] = o2;
    *(int4*)&g_off[base + 12] = o3;
    if (t == 1023) g_Etot = pre + local[15] + cv[15];
}

// launch #3
__global__ void k_scatter(const int* __restrict__ ei, const float* __restrict__ pos,
                          const int* __restrict__ z) {
    int e = blockIdx.x * 256 + threadIdx.x;
    if (e >= NE) return;
    int src = ei[e], dst = ei[NE + e];
    float vx = pos[src * 3 + 0] - pos[dst * 3 + 0];
    float vy = pos[src * 3 + 1] - pos[dst * 3 + 1];
    float vz = pos[src * 3 + 2] - pos[dst * 3 + 2];
    float d = sqrtf(vx * vx + vy * vy + vz * vz);
    bool selfe = (src == dst);
    if (!selfe && !(d < 4.5f)) return;
    int slot = g_off[src] + atomicAdd(&g_fill[src], 1);
    g_erec[slot] = make_float4(vx, vy, vz, d);
    g_ez[slot] = z[dst] | (selfe ? (int)0x80000000 : 0);
}

// launch #4: per-edge dp projections (4 edges per warp iteration)
#define EDP_SMEM ((32 * 384 + 384) * 4)
#define EDP_BLOCKS 296
__global__ __launch_bounds__(256)
void k_edgedp() {
    extern __shared__ float sdp[];
    float* sW = sdp;
    float* sb = sdp + 32 * 384;
    int tid = threadIdx.x;

    #pragma unroll 8
    for (int i = tid; i < 32 * 384; i += 256) sW[i] = g_Wt[i];
    if (tid < 128) {
        sb[tid] = g_db[tid];
        sb[128 + tid] = g_db[128 + tid];
        sb[256 + tid] = g_db[256 + tid];
    }
    __syncthreads();

    int E = g_Etot;
    int lane = tid & 31, w = tid >> 5;
    float mean = (float)RBF_START + (float)lane * (float)((1.0 - RBF_START) / 31.0);
    float bias0[12];
    #pragma unroll
    for (int c = 0; c < 12; c++) bias0[c] = sb[lane + 32 * c];

    int gw = blockIdx.x * 8 + w;
    int nw = EDP_BLOCKS * 8;
    for (int e0 = gw * 4; e0 < E; e0 += nw * 4) {
        float attr[4];
        #pragma unroll
        for (int i = 0; i < 4; i++) {
            int e = e0 + i;
            if (e < E) {
                float d = g_erec[e].w;
                float cut = 0.5f * (cosf(d * (float)PI_OVER_C) + 1.0f);
                float gex = expf(-(float)RBF_ALPHA * d);
                float diff = gex - mean;
                attr[i] = cut * expf(-(float)RBF_BETA * diff * diff);
            } else attr[i] = 0.f;
        }

        float acc[4][12];
        #pragma unroll
        for (int i = 0; i < 4; i++)
            #pragma unroll
            for (int c = 0; c < 12; c++) acc[i][c] = bias0[c];

        #pragma unroll
        for (int r = 0; r < 32; r++) {
            float a0 = __shfl_sync(0xffffffffu, attr[0], r);
            float a1 = __shfl_sync(0xffffffffu, attr[1], r);
            float a2 = __shfl_sync(0xffffffffu, attr[2], r);
            float a3 = __shfl_sync(0xffffffffu, attr[3], r);
            const float* wr = sW + r * 384 + lane;
            #pragma unroll
            for (int c = 0; c < 12; c++) {
                float wv = wr[32 * c];
                acc[0][c] = fmaf(a0, wv, acc[0][c]);
                acc[1][c] = fmaf(a1, wv, acc[1][c]);
                acc[2][c] = fmaf(a2, wv, acc[2][c]);
                acc[3][c] = fmaf(a3, wv, acc[3][c]);
            }
        }
        #pragma unroll
        for (int i = 0; i < 4; i++) {
            int e = e0 + i;
            if (e < E) {
                float* out = g_edp + (size_t)e * 384 + lane;
                #pragma unroll
                for (int c = 0; c < 12; c++) out[32 * c] = acc[i][c];
            }
        }
    }
}

// launch #5: gather + tensor-norm + layernorm(128)
__global__ void k_gather(const int* __restrict__ z,
                         const float* __restrict__ gam, const float* __restrict__ bet) {
    int n = blockIdx.x, h = threadIdx.x;
    __shared__ float red[4];

    int cnt = g_cnt[n];
    int off = g_off[n];
    int zn = z[n];
    float Un = g_U[(zn << 7) + h];

    float a = 0.f, bx = 0.f, by = 0.f, bz = 0.f;
    float xx = 0.f, yy = 0.f, zz = 0.f, xy = 0.f, xz = 0.f, yz = 0.f;

    for (int j = 0; j < cnt; j++) {
        int e = off + j;
        float4 rec = g_erec[e];
        int ezd = g_ez[e];
        bool selfe = (ezd < 0);
        int zdst = ezd & 127;
        float d = rec.w;
        float cut = 0.5f * (cosf(d * (float)PI_OVER_C) + 1.0f);
        float inv = selfe ? 1.0f : (1.0f / d);
        float vx = rec.x * inv, vy = rec.y * inv, vz = rec.z * inv;

        const float* dp = g_edp + (size_t)e * 384 + h;
        float d1 = dp[0], d2 = dp[128], d3 = dp[256];
        float C = cut * (Un + g_V[(zdst << 7) + h]);

        float ai = d1 * C, cb = d2 * C, cs = d3 * C;
        a  += ai;
        bx += cb * vx; by += cb * vy; bz += cb * vz;
        xx += cs * vx * vx; yy += cs * vy * vy; zz += cs * vz * vz;
        xy += cs * vx * vy; xz += cs * vx * vz; yz += cs * vy * vz;
    }

    int i = (n << 7) + h;
    float vals[10] = {a, bx, by, bz, xx, yy, zz, xy, xz, yz};
    #pragma unroll
    for (int p = 0; p < 10; p++) {
        bf16 hh, ll;
        split1(vals[p], hh, ll);
        g_accH[(size_t)p * (NN * 128) + i] = hh;
        g_accL[(size_t)p * (NN * 128) + i] = ll;
    }

    float tr = xx + yy + zz;
    float ms = xx * xx + yy * yy + zz * zz + 2.f * (xy * xy + xz * xz + yz * yz);
    float tn = 3.f * a * a + 2.f * (bx * bx + by * by + bz * bz) + ms - tr * tr * (1.f / 3.f);

    float v = tn;
    #pragma unroll
    for (int o = 16; o; o >>= 1) v += __shfl_xor_sync(0xffffffffu, v, o);
    if ((h & 31) == 0) red[h >> 5] = v;
    __syncthreads();
    float mean = (red[0] + red[1] + red[2] + red[3]) * (1.f / 128.f);
    float dev = tn - mean;
    v = dev * dev;
    #pragma unroll
    for (int o = 16; o; o >>= 1) v += __shfl_xor_sync(0xffffffffu, v, o);
    __syncthreads();
    if ((h & 31) == 0) red[h >> 5] = v;
    __syncthreads();
    float var = (red[0] + red[1] + red[2] + red[3]) * (1.f / 128.f);
    float T = dev * rsqrtf(var + 1e-5f) * gam[h] + bet[h];
    bf16 th, tl;
    split1(T, th, tl);
    g_TH[i] = th; g_TL[i] = tl;

    if (h == 0) { g_cnt[n] = 0; g_fill[n] = 0; }
}

// ---------------- launch ----------------
extern "C" void kernel_launch(void* const* d_in, const int* in_sizes, int n_in,
                              void* d_out, int out_size) {
    const int*   z      = (const int*)d_in[0];
    const float* pos    = (const float*)d_in[1];
    const int*   ei     = (const int*)d_in[3];
    const float* emb_w  = (const float*)d_in[4];
    const float* emb2_w = (const float*)d_in[5];
    const float* emb2_b = (const float*)d_in[6];
    const float* dp1w   = (const float*)d_in[7];
    const float* dp1b   = (const float*)d_in[8];
    const float* dp2w   = (const float*)d_in[9];
    const float* dp2b   = (const float*)d_in[10];
    const float* dp3w   = (const float*)d_in[11];
    const float* dp3b   = (const float*)d_in[12];
    const float* lt0w   = (const float*)d_in[13];
    const float* lt1w   = (const float*)d_in[14];
    const float* lt2w   = (const float*)d_in[15];
    const float* ls0w   = (const float*)d_in[16];
    const float* ls0b   = (const float*)d_in[17];
    const float* ls1w   = (const float*)d_in[18];
    const float* ls1b   = (const float*)d_in[19];
    const float* ing    = (const float*)d_in[20];
    const float* inb    = (const float*)d_in[21];
    const float* linw   = (const float*)d_in[22];
    const float* linb   = (const float*)d_in[23];
    const float* ong    = (const float*)d_in[24];
    const float* onb    = (const float*)d_in[25];
    const float* ol1w   = (const float*)d_in[26];
    const float* ol1b   = (const float*)d_in[27];
    const float* ol2w   = (const float*)d_in[28];
    const float* ol2b   = (const float*)d_in[29];
    float* y = (float*)d_out;

    cudaFuncSetAttribute(tg_mixls0, cudaFuncAttributeMaxDynamicSharedMemorySize, TG_SMEM);
    cudaFuncSetAttribute(tg_ls1, cudaFuncAttributeMaxDynamicSharedMemorySize, TG_SMEM);
    cudaFuncSetAttribute(tg_tail, cudaFuncAttributeMaxDynamicSharedMemorySize, TG_SMEM);
    cudaFuncSetAttribute(k_edgedp, cudaFuncAttributeMaxDynamicSharedMemorySize, EDP_SMEM);

    k_count<<<1296, 256>>>(ei, pos, emb_w, emb2_w, emb2_b,
                           dp1w, dp1b, dp2w, dp2b, dp3w, dp3b,
                           ls0w, ls1w, linw, lt0w, lt1w, lt2w, ol1w);
    k_scan<<<1, 1024>>>();
    k_scatter<<<NE / 256, 256>>>(ei, pos, z);
    k_edgedp<<<EDP_BLOCKS, 256, EDP_SMEM>>>();
    k_gather<<<NN, 128>>>(z, ing, inb);
    tg_mixls0<<<1536, 256, TG_SMEM>>>(ls0b);
    tg_ls1<<<dim3(NN / 128, 3), 256, TG_SMEM>>>(ls1b);
    tg_tail<<<NN / 128, 256, TG_SMEM>>>(ong, onb, linb, ol1b, ol2w, ol2b, y);
}

// round 15
// speedup vs baseline: 1.0162x; 1.0162x over previous
#include <cuda_runtime.h>
#include <cuda_bf16.h>
#include <math.h>
#include <stdint.h>

#define NN 16384
#define NE 65536
typedef __nv_bfloat16 bf16;

// ---------------- fp32 scratch ----------------
static __device__ __align__(256) float g_U[128 * 128];
static __device__ __align__(256) float g_V[128 * 128];
static __device__ __align__(256) float g_NR[NN * 384];
static __device__ __align__(256) float g_mix[10][NN * 128];
static __device__ __align__(256) float g_Wt[32 * 384];
static __device__ __align__(256) float g_db[384];
static __device__ __align__(256) float g_edp[(size_t)NE * 384];
static __device__ int g_Etot;

// ---------------- bf16 hi/lo activations ----------------
static __device__ __align__(256) bf16 g_accH[10 * NN * 128], g_accL[10 * NN * 128];
static __device__ __align__(256) bf16 g_TH[NN * 128],  g_TL[NN * 128];
static __device__ __align__(256) bf16 g_H1H[NN * 256], g_H1L[NN * 256];
static __device__ __align__(256) bf16 g_XNH[NN * 384], g_XNL[NN * 384];

// ---------------- bf16 hi/lo weights ----------------
static __device__ __align__(256) bf16 w_ls0H[256 * 128], w_ls0L[256 * 128];
static __device__ __align__(256) bf16 w_ls1H[384 * 256], w_ls1L[384 * 256];
static __device__ __align__(256) bf16 w_linH[128 * 384], w_linL[128 * 384];
static __device__ __align__(256) bf16 w_ltH[3 * 128 * 128], w_ltL[3 * 128 * 128];
static __device__ __align__(256) bf16 w_ol1H[64 * 128], w_ol1L[64 * 128];

// ---------------- CSR edge compaction ----------------
static __device__ __align__(256) int    g_cnt[NN];
static __device__ __align__(256) int    g_off[NN];
static __device__ __align__(256) int    g_fill[NN];
static __device__ __align__(256) float4 g_erec[NE];
static __device__ __align__(256) int    g_ez[NE];

__device__ __forceinline__ float silu(float x) { return x / (1.f + expf(-x)); }
__device__ __forceinline__ void split1(float v, bf16& h, bf16& l) {
    h = __float2bfloat16(v);
    l = __float2bfloat16(v - __bfloat162float(h));
}

#define RBF_START 0.011108996538242306
#define RBF_BETA  (1.0 / ((0.0625 * (1.0 - RBF_START)) * (0.0625 * (1.0 - RBF_START))))
#define RBF_ALPHA (5.0 / 4.5)
#define PI_OVER_C 0.6981317007977318

// =================== MMA plumbing ===================
__device__ __forceinline__ uint32_t smem_u32(const void* p) {
    uint32_t a;
    asm("{ .reg .u64 t; cvta.to.shared.u64 t, %1; cvt.u32.u64 %0, t; }" : "=r"(a) : "l"(p));
    return a;
}
__device__ __forceinline__ void ldm_x4(uint32_t addr, uint32_t* r) {
    asm volatile("ldmatrix.sync.aligned.m8n8.x4.shared.b16 {%0,%1,%2,%3}, [%4];"
                 : "=r"(r[0]), "=r"(r[1]), "=r"(r[2]), "=r"(r[3]) : "r"(addr));
}
__device__ __forceinline__ void mma16816(float* c, const uint32_t* a, const uint32_t* b) {
    asm volatile("mma.sync.aligned.m16n8k16.row.col.f32.bf16.bf16.f32 "
                 "{%0,%1,%2,%3}, {%4,%5,%6,%7}, {%8,%9}, {%0,%1,%2,%3};"
                 : "+f"(c[0]), "+f"(c[1]), "+f"(c[2]), "+f"(c[3])
                 : "r"(a[0]), "r"(a[1]), "r"(a[2]), "r"(a[3]), "r"(b[0]), "r"(b[1]));
}
__device__ __forceinline__ void cpa16(uint32_t s, const void* g) {
    asm volatile("cp.async.cg.shared.global [%0], [%1], 16;" :: "r"(s), "l"(g));
}
#define CP_COMMIT() asm volatile("cp.async.commit_group;")
#define CP_WAIT0()  asm volatile("cp.async.wait_group 0;" ::: "memory")

#define TPAD 136
#define SM_A (128 * TPAD * 2)
#define SM_W (64 * TPAD * 2)
#define TG_SMEM (2 * SM_A + 2 * SM_W)   // 104448 -> 2 CTAs/SM

template <int OUT, int FT>
__device__ __forceinline__ void mma_gemm_bf(
    int bx, int by,
    const bf16* __restrict__ AH, const bf16* __restrict__ AL,
    const bf16* __restrict__ WH, const bf16* __restrict__ WL,
    const float* __restrict__ bias,
    float* __restrict__ C, bf16* __restrict__ CH, bf16* __restrict__ CL,
    int K, int F, bool act) {
    extern __shared__ __align__(16) char smem[];
    const uint32_t aH_u = smem_u32(smem);
    const uint32_t aL_u = aH_u + SM_A;
    const uint32_t wH_u = aH_u + 2 * SM_A;
    const uint32_t wL_u = wH_u + SM_W;

    const int tid = threadIdx.x, lane = tid & 31, wid = tid >> 5;
    const int wm = wid & 3, wn = wid >> 2;
    const int m0 = bx << 7;
    const int f0 = by * (64 * FT);

    float c[FT][2][4][4];
    #pragma unroll
    for (int ft = 0; ft < FT; ft++)
        #pragma unroll
        for (int i = 0; i < 2; i++)
            #pragma unroll
            for (int j = 0; j < 4; j++)
                #pragma unroll
                for (int q = 0; q < 4; q++) c[ft][i][j][q] = 0.f;

    const int a_row = wm * 32 + (lane & 15);
    const int a_col = (lane >> 4) << 3;
    const int b_row = wn * 32 + (lane & 7) + ((lane >> 4) << 3);
    const int b_col = ((lane >> 3) & 1) << 3;

    for (int kc = 0; kc < K; kc += 128) {
        __syncthreads();
        #pragma unroll
        for (int i = tid; i < 2048; i += 256) {
            int r = i >> 4, c8 = (i & 15) << 3;
            uint32_t so = (uint32_t)(r * TPAD + c8) * 2;
            size_t go = (size_t)(m0 + r) * K + kc + c8;
            cpa16(aH_u + so, AH + go);
            cpa16(aL_u + so, AL + go);
        }
        #pragma unroll
        for (int i = tid; i < 1024; i += 256) {
            int r = i >> 4, c8 = (i & 15) << 3;
            uint32_t so = (uint32_t)(r * TPAD + c8) * 2;
            size_t go = (size_t)(f0 + r) * K + kc + c8;
            cpa16(wH_u + so, WH + go);
            cpa16(wL_u + so, WL + go);
        }
        CP_COMMIT();
        CP_WAIT0();
        __syncthreads();

        #pragma unroll
        for (int ft = 0; ft < FT; ft++) {
            if (ft > 0) {
                __syncthreads();
                #pragma unroll
                for (int i = tid; i < 1024; i += 256) {
                    int r = i >> 4, c8 = (i & 15) << 3;
                    uint32_t so = (uint32_t)(r * TPAD + c8) * 2;
                    size_t go = (size_t)(f0 + ft * 64 + r) * K + kc + c8;
                    cpa16(wH_u + so, WH + go);
                    cpa16(wL_u + so, WL + go);
                }
                CP_COMMIT();
                CP_WAIT0();
                __syncthreads();
            }
            #pragma unroll
            for (int ks = 0; ks < 8; ks++) {
                uint32_t ah[2][4], al[2][4];
                #pragma unroll
                for (int mf = 0; mf < 2; mf++) {
                    uint32_t off = (uint32_t)((a_row + mf * 16) * TPAD + a_col + ks * 16) * 2;
                    ldm_x4(aH_u + off, ah[mf]);
                    ldm_x4(aL_u + off, al[mf]);
                }
                #pragma unroll
                for (int nfp = 0; nfp < 2; nfp++) {
                    uint32_t boff = (uint32_t)((b_row + nfp * 16) * TPAD + b_col + ks * 16) * 2;
                    uint32_t bh[4], bl[4];
                    ldm_x4(wH_u + boff, bh);
                    ldm_x4(wL_u + boff, bl);
                    #pragma unroll
                    for (int mf = 0; mf < 2; mf++) {
                        mma16816(c[ft][mf][2 * nfp], ah[mf], bh);
                        mma16816(c[ft][mf][2 * nfp], ah[mf], bl);
                        mma16816(c[ft][mf][2 * nfp], al[mf], bh);
                        mma16816(c[ft][mf][2 * nfp + 1], ah[mf], bh + 2);
                        mma16816(c[ft][mf][2 * nfp + 1], ah[mf], bl + 2);
                        mma16816(c[ft][mf][2 * nfp + 1], al[mf], bh + 2);
                    }
                }
            }
        }
    }

    #pragma unroll
    for (int ft = 0; ft < FT; ft++) {
        #pragma unroll
        for (int mf = 0; mf < 2; mf++) {
            #pragma unroll
            for (int nf = 0; nf < 4; nf++) {
                int grow = m0 + wm * 32 + mf * 16 + (lane >> 2);
                int gcol = f0 + ft * 64 + wn * 32 + nf * 8 + ((lane & 3) << 1);
                float b0 = bias ? bias[gcol] : 0.f;
                float b1 = bias ? bias[gcol + 1] : 0.f;
                float v0 = c[ft][mf][nf][0] + b0, v1 = c[ft][mf][nf][1] + b1;
                float v2 = c[ft][mf][nf][2] + b0, v3 = c[ft][mf][nf][3] + b1;
                if (act) { v0 = silu(v0); v1 = silu(v1); v2 = silu(v2); v3 = silu(v3); }
                if (OUT == 0) {
                    *(float2*)&C[(size_t)grow * F + gcol] = make_float2(v0, v1);
                    *(float2*)&C[(size_t)(grow + 8) * F + gcol] = make_float2(v2, v3);
                } else {
                    bf16 h0, l0, h1, l1;
                    split1(v0, h0, l0); split1(v1, h1, l1);
                    *(__nv_bfloat162*)&CH[(size_t)grow * F + gcol] = __halves2bfloat162(h0, h1);
                    *(__nv_bfloat162*)&CL[(size_t)grow * F + gcol] = __halves2bfloat162(l0, l1);
                    split1(v2, h0, l0); split1(v3, h1, l1);
                    *(__nv_bfloat162*)&CH[(size_t)(grow + 8) * F + gcol] = __halves2bfloat162(h0, h1);
                    *(__nv_bfloat162*)&CL[(size_t)(grow + 8) * F + gcol] = __halves2bfloat162(l0, l1);
                }
            }
        }
    }
}

__global__ __launch_bounds__(256, 2)
void tg_mixls0(const float* __restrict__ ls0b) {
    int bid = blockIdx.x;
    if (bid < 1280) {
        int plane = bid >> 7;
        int sel = (plane == 0) ? 0 : (plane < 4 ? 1 : 2);
        mma_gemm_bf<0, 2>(bid, 0, g_accH, g_accL, w_ltH + sel * 16384, w_ltL + sel * 16384,
                          nullptr, &g_mix[0][0], nullptr, nullptr, 128, 128, false);
    } else {
        int b = bid - 1280;
        mma_gemm_bf<1, 2>(b & 127, b >> 7, g_TH, g_TL, w_ls0H, w_ls0L, ls0b,
                          nullptr, g_H1H, g_H1L, 128, 256, true);
    }
}
__global__ __launch_bounds__(256, 2)
void tg_ls1(const float* __restrict__ b) {
    mma_gemm_bf<0, 2>(blockIdx.x, blockIdx.y, g_H1H, g_H1L, w_ls1H, w_ls1L, b,
                      g_NR, nullptr, nullptr, 256, 384, true);
}

// =================== fused tail: lin GEMM -> ol1 GEMM -> final dot ===================
__global__ __launch_bounds__(256, 2)
void tg_tail(const float* __restrict__ linb, const float* __restrict__ ol1b,
             const float* __restrict__ ol2w, const float* __restrict__ ol2b,
             float* __restrict__ y) {
    extern __shared__ __align__(16) char smem[];
    const uint32_t aH_u = smem_u32(smem);
    const uint32_t aL_u = aH_u + SM_A;
    const uint32_t wH_u = aH_u + 2 * SM_A;
    const uint32_t wL_u = wH_u + SM_W;
    __shared__ float ypart[128];

    const int tid = threadIdx.x, lane = tid & 31, wid = tid >> 5;
    const int wm = wid & 3, wn = wid >> 2;
    const int m0 = blockIdx.x << 7;

    const int a_row = wm * 32 + (lane & 15);
    const int a_col = (lane >> 4) << 3;
    const int b_row = wn * 32 + (lane & 7) + ((lane >> 4) << 3);
    const int b_col = ((lane >> 3) & 1) << 3;

    float c[2][2][4][4];
    #pragma unroll
    for (int ft = 0; ft < 2; ft++)
        #pragma unroll
        for (int i = 0; i < 2; i++)
            #pragma unroll
            for (int j = 0; j < 4; j++)
                #pragma unroll
                for (int q = 0; q < 4; q++) c[ft][i][j][q] = 0.f;

    for (int kc = 0; kc < 384; kc += 128) {
        __syncthreads();
        #pragma unroll
        for (int i = tid; i < 2048; i += 256) {
            int r = i >> 4, c8 = (i & 15) << 3;
            uint32_t so = (uint32_t)(r * TPAD + c8) * 2;
            size_t go = (size_t)(m0 + r) * 384 + kc + c8;
            cpa16(aH_u + so, g_XNH + go);
            cpa16(aL_u + so, g_XNL + go);
        }
        #pragma unroll
        for (int i = tid; i < 1024; i += 256) {
            int r = i >> 4, c8 = (i & 15) << 3;
            uint32_t so = (uint32_t)(r * TPAD + c8) * 2;
            size_t go = (size_t)r * 384 + kc + c8;
            cpa16(wH_u + so, w_linH + go);
            cpa16(wL_u + so, w_linL + go);
        }
        CP_COMMIT();
        CP_WAIT0();
        __syncthreads();

        #pragma unroll
        for (int ft = 0; ft < 2; ft++) {
            if (ft > 0) {
                __syncthreads();
                #pragma unroll
                for (int i = tid; i < 1024; i += 256) {
                    int r = i >> 4, c8 = (i & 15) << 3;
                    uint32_t so = (uint32_t)(r * TPAD + c8) * 2;
                    size_t go = (size_t)(64 + r) * 384 + kc + c8;
                    cpa16(wH_u + so, w_linH + go);
                    cpa16(wL_u + so, w_linL + go);
                }
                CP_COMMIT();
                CP_WAIT0();
                __syncthreads();
            }
            #pragma unroll
            for (int ks = 0; ks < 8; ks++) {
                uint32_t ah[2][4], al[2][4];
                #pragma unroll
                for (int mf = 0; mf < 2; mf++) {
                    uint32_t off = (uint32_t)((a_row + mf * 16) * TPAD + a_col + ks * 16) * 2;
                    ldm_x4(aH_u + off, ah[mf]);
                    ldm_x4(aL_u + off, al[mf]);
                }
                #pragma unroll
                for (int nfp = 0; nfp < 2; nfp++) {
                    uint32_t boff = (uint32_t)((b_row + nfp * 16) * TPAD + b_col + ks * 16) * 2;
                    uint32_t bh[4], bl[4];
                    ldm_x4(wH_u + boff, bh);
                    ldm_x4(wL_u + boff, bl);
                    #pragma unroll
                    for (int mf = 0; mf < 2; mf++) {
                        mma16816(c[ft][mf][2 * nfp], ah[mf], bh);
                        mma16816(c[ft][mf][2 * nfp], ah[mf], bl);
                        mma16816(c[ft][mf][2 * nfp], al[mf], bh);
                        mma16816(c[ft][mf][2 * nfp + 1], ah[mf], bh + 2);
                        mma16816(c[ft][mf][2 * nfp + 1], ah[mf], bl + 2);
                        mma16816(c[ft][mf][2 * nfp + 1], al[mf], bh + 2);
                    }
                }
            }
        }
    }

    __syncthreads();
    #pragma unroll
    for (int ft = 0; ft < 2; ft++) {
        #pragma unroll
        for (int mf = 0; mf < 2; mf++) {
            #pragma unroll
            for (int nf = 0; nf < 4; nf++) {
                int lrow = wm * 32 + mf * 16 + (lane >> 2);
                int lcol = ft * 64 + wn * 32 + nf * 8 + ((lane & 3) << 1);
                float b0 = linb[lcol], b1 = linb[lcol + 1];
                float v0 = silu(c[ft][mf][nf][0] + b0);
                float v1 = silu(c[ft][mf][nf][1] + b1);
                float v2 = silu(c[ft][mf][nf][2] + b0);
                float v3 = silu(c[ft][mf][nf][3] + b1);
                bf16 h0, l0, h1, l1;
                split1(v0, h0, l0); split1(v1, h1, l1);
                *(__nv_bfloat162*)(smem + (size_t)(lrow * TPAD + lcol) * 2) =
                    __halves2bfloat162(h0, h1);
                *(__nv_bfloat162*)(smem + SM_A + (size_t)(lrow * TPAD + lcol) * 2) =
                    __halves2bfloat162(l0, l1);
                split1(v2, h0, l0); split1(v3, h1, l1);
                *(__nv_bfloat162*)(smem + (size_t)((lrow + 8) * TPAD + lcol) * 2) =
                    __halves2bfloat162(h0, h1);
                *(__nv_bfloat162*)(smem + SM_A + (size_t)((lrow + 8) * TPAD + lcol) * 2) =
                    __halves2bfloat162(l0, l1);
            }
        }
    }
    #pragma unroll
    for (int i = tid; i < 1024; i += 256) {
        int r = i >> 4, c8 = (i & 15) << 3;
        if (r < 64) {
            uint32_t so = (uint32_t)(r * TPAD + c8) * 2;
            cpa16(wH_u + so, w_ol1H + r * 128 + c8);
            cpa16(wL_u + so, w_ol1L + r * 128 + c8);
        }
    }
    CP_COMMIT();
    CP_WAIT0();
    if (tid < 128) ypart[tid] = 0.f;
    __syncthreads();

    float c2[2][4][4];
    #pragma unroll
    for (int i = 0; i < 2; i++)
        #pragma unroll
        for (int j = 0; j < 4; j++)
            #pragma unroll
            for (int q = 0; q < 4; q++) c2[i][j][q] = 0.f;

    #pragma unroll
    for (int ks = 0; ks < 8; ks++) {
        uint32_t ah[2][4], al[2][4];
        #pragma unroll
        for (int mf = 0; mf < 2; mf++) {
            uint32_t off = (uint32_t)((a_row + mf * 16) * TPAD + a_col + ks * 16) * 2;
            ldm_x4(aH_u + off, ah[mf]);
            ldm_x4(aL_u + off, al[mf]);
        }
        #pragma unroll
        for (int nfp = 0; nfp < 2; nfp++) {
            uint32_t boff = (uint32_t)((b_row + nfp * 16) * TPAD + b_col + ks * 16) * 2;
            uint32_t bh[4], bl[4];
            ldm_x4(wH_u + boff, bh);
            ldm_x4(wL_u + boff, bl);
            #pragma unroll
            for (int mf = 0; mf < 2; mf++) {
                mma16816(c2[mf][2 * nfp], ah[mf], bh);
                mma16816(c2[mf][2 * nfp], ah[mf], bl);
                mma16816(c2[mf][2 * nfp], al[mf], bh);
                mma16816(c2[mf][2 * nfp + 1], ah[mf], bh + 2);
                mma16816(c2[mf][2 * nfp + 1], ah[mf], bl + 2);
                mma16816(c2[mf][2 * nfp + 1], al[mf], bh + 2);
            }
        }
    }

    #pragma unroll
    for (int mf = 0; mf < 2; mf++) {
        float pr0 = 0.f, pr8 = 0.f;
        #pragma unroll
        for (int nf = 0; nf < 4; nf++) {
            int gcol = wn * 32 + nf * 8 + ((lane & 3) << 1);
            float b0 = ol1b[gcol], b1 = ol1b[gcol + 1];
            float w0 = ol2w[gcol], w1 = ol2w[gcol + 1];
            pr0 += silu(c2[mf][nf][0] + b0) * w0 + silu(c2[mf][nf][1] + b1) * w1;
            pr8 += silu(c2[mf][nf][2] + b0) * w0 + silu(c2[mf][nf][3] + b1) * w1;
        }
        int lrow = wm * 32 + mf * 16 + (lane >> 2);
        atomicAdd(&ypart[lrow], pr0);
        atomicAdd(&ypart[lrow + 8], pr8);
    }
    __syncthreads();
    if (tid < 128) y[m0 + tid] = ypart[tid] + ol2b[0];
}

// ---------------- weight pre-split ----------------
__global__ void k_wprep(const float* __restrict__ ls0w, const float* __restrict__ ls1w,
                        const float* __restrict__ linw, const float* __restrict__ lt0w,
                        const float* __restrict__ lt1w, const float* __restrict__ lt2w,
                        const float* __restrict__ ol1w) {
    int j = blockIdx.x * 256 + threadIdx.x;
    const float* src; bf16 *dh, *dl;
    if (j < 32768) { src = ls0w; dh = w_ls0H; dl = w_ls0L; }
    else if ((j -= 32768) < 98304) { src = ls1w; dh = w_ls1H; dl = w_ls1L; }
    else if ((j -= 98304) < 49152) { src = linw; dh = w_linH; dl = w_linL; }
    else if ((j -= 49152) < 16384) { src = lt0w; dh = w_ltH; dl = w_ltL; }
    else if ((j -= 16384) < 16384) { src = lt1w; dh = w_ltH + 16384; dl = w_ltL + 16384; }
    else if ((j -= 16384) < 16384) { src = lt2w; dh = w_ltH + 32768; dl = w_ltL + 32768; }
    else if ((j -= 16384) < 8192)  { src = ol1w; dh = w_ol1H; dl = w_ol1L; }
    else return;
    bf16 h, l;
    split1(src[j], h, l);
    dh[j] = h; dl[j] = l;
}

// =================== launch #1: edge count + U/V tables + dp transpose ===================
__global__ void k_count(const int* __restrict__ ei, const float* __restrict__ pos,
                        const float* __restrict__ emb_w, const float* __restrict__ emb2_w,
                        const float* __restrict__ emb2_b,
                        const float* __restrict__ dp1w, const float* __restrict__ dp1b,
                        const float* __restrict__ dp2w, const float* __restrict__ dp2b,
                        const float* __restrict__ dp3w, const float* __restrict__ dp3b) {
    int b = blockIdx.x;
    if (b < 256) {
        int e = b * 256 + threadIdx.x;
        int src = ei[e], dst = ei[NE + e];
        float vx = pos[src * 3 + 0] - pos[dst * 3 + 0];
        float vy = pos[src * 3 + 1] - pos[dst * 3 + 1];
        float vz = pos[src * 3 + 2] - pos[dst * 3 + 2];
        float d = sqrtf(vx * vx + vy * vy + vz * vz);
        if (src == dst || d < 4.5f) atomicAdd(&g_cnt[src], 1);
    } else if (b < 320) {
        int zt = ((b - 256) << 1) | (threadIdx.x >> 7);
        int h = threadIdx.x & 127;
        float u = emb2_b[h];
        float v = 0.f;
        #pragma unroll 4
        for (int k = 0; k < 128; k++) {
            float e = emb_w[zt * 128 + k];
            u = fmaf(e, emb2_w[h * 256 + k], u);
            v = fmaf(e, emb2_w[h * 256 + 128 + k], v);
        }
        g_U[zt * 128 + h] = u;
        g_V[zt * 128 + h] = v;
    } else {
        int j = (b - 320) * 256 + threadIdx.x;   // 0..12287
        int r = j / 384, col = j - r * 384;
        float v = col < 128 ? dp1w[col * 32 + r]
                : col < 256 ? dp2w[(col - 128) * 32 + r]
                            : dp3w[(col - 256) * 32 + r];
        g_Wt[j] = v;
        if (j < 384)
            g_db[j] = j < 128 ? dp1b[j] : j < 256 ? dp2b[j - 128] : dp3b[j - 256];
    }
}

// launch #2: exclusive scan + total edge count
__global__ void k_scan() {
    __shared__ int ws[32];
    int t = threadIdx.x;
    int lane = t & 31, w = t >> 5;
    int base = t * 16;
    int4 v0 = *(int4*)&g_cnt[base];
    int4 v1 = *(int4*)&g_cnt[base + 4];
    int4 v2 = *(int4*)&g_cnt[base + 8];
    int4 v3 = *(int4*)&g_cnt[base + 12];
    int cv[16] = {v0.x, v0.y, v0.z, v0.w, v1.x, v1.y, v1.z, v1.w,
                  v2.x, v2.y, v2.z, v2.w, v3.x, v3.y, v3.z, v3.w};
    int local[16];
    int s = 0;
    #pragma unroll
    for (int i = 0; i < 16; i++) { local[i] = s; s += cv[i]; }
    int inc = s;
    #pragma unroll
    for (int off = 1; off < 32; off <<= 1) {
        int x = __shfl_up_sync(0xffffffffu, inc, off);
        if (lane >= off) inc += x;
    }
    if (lane == 31) ws[w] = inc;
    __syncthreads();
    if (w == 0) {
        int wi = ws[lane];
        #pragma unroll
        for (int off = 1; off < 32; off <<= 1) {
            int x = __shfl_up_sync(0xffffffffu, wi, off);
            if (lane >= off) wi += x;
        }
        ws[lane] = wi;
    }
    __syncthreads();
    int warp_pre = (w == 0) ? 0 : ws[w - 1];
    int pre = warp_pre + inc - s;
    int4 o0 = make_int4(pre + local[0], pre + local[1], pre + local[2], pre + local[3]);
    int4 o1 = make_int4(pre + local[4], pre + local[5], pre + local[6], pre + local[7]);
    int4 o2 = make_int4(pre + local[8], pre + local[9], pre + local[10], pre + local[11]);
    int4 o3 = make_int4(pre + local[12], pre + local[13], pre + local[14], pre + local[15]);
    *(int4*)&g_off[base] = o0;
    *(int4*)&g_off[base + 4] = o1;
    *(int4*)&g_off[base + 8] = o2;
    *(int4*)&g_off[base + 12] = o3;
    if (t == 1023) g_Etot = pre + local[15] + cv[15];
}

// launch #3
__global__ void k_scatter(const int* __restrict__ ei, const float* __restrict__ pos,
                          const int* __restrict__ z) {
    int e = blockIdx.x * 256 + threadIdx.x;
    if (e >= NE) return;
    int src = ei[e], dst = ei[NE + e];
    float vx = pos[src * 3 + 0] - pos[dst * 3 + 0];
    float vy = pos[src * 3 + 1] - pos[dst * 3 + 1];
    float vz = pos[src * 3 + 2] - pos[dst * 3 + 2];
    float d = sqrtf(vx * vx + vy * vy + vz * vz);
    bool selfe = (src == dst);
    if (!selfe && !(d < 4.5f)) return;
    int slot = g_off[src] + atomicAdd(&g_fill[src], 1);
    g_erec[slot] = make_float4(vx, vy, vz, d);
    g_ez[slot] = z[dst] | (selfe ? (int)0x80000000 : 0);
}

// launch #4: per-edge dp projections. 2 edges per warp iteration (reg/occ balance).
#define EDP_SMEM ((32 * 384 + 384) * 4)
#define EDP_BLOCKS 444
__global__ __launch_bounds__(256)
void k_edgedp() {
    extern __shared__ float sdp[];
    float* sW = sdp;
    float* sb = sdp + 32 * 384;
    int tid = threadIdx.x;

    #pragma unroll 8
    for (int i = tid; i < 32 * 384; i += 256) sW[i] = g_Wt[i];
    if (tid < 128) {
        sb[tid] = g_db[tid];
        sb[128 + tid] = g_db[128 + tid];
        sb[256 + tid] = g_db[256 + tid];
    }
    __syncthreads();

    int E = g_Etot;
    int lane = tid & 31, w = tid >> 5;
    float mean = (float)RBF_START + (float)lane * (float)((1.0 - RBF_START) / 31.0);
    float bias0[12];
    #pragma unroll
    for (int c = 0; c < 12; c++) bias0[c] = sb[lane + 32 * c];

    int gw = blockIdx.x * 8 + w;
    int nw = EDP_BLOCKS * 8;
    for (int e0 = gw * 2; e0 < E; e0 += nw * 2) {
        float attr[2];
        #pragma unroll
        for (int i = 0; i < 2; i++) {
            int e = e0 + i;
            if (e < E) {
                float d = g_erec[e].w;
                float cut = 0.5f * (cosf(d * (float)PI_OVER_C) + 1.0f);
                float gex = expf(-(float)RBF_ALPHA * d);
                float diff = gex - mean;
                attr[i] = cut * expf(-(float)RBF_BETA * diff * diff);
            } else attr[i] = 0.f;
        }

        float acc[2][12];
        #pragma unroll
        for (int i = 0; i < 2; i++)
            #pragma unroll
            for (int c = 0; c < 12; c++) acc[i][c] = bias0[c];

        #pragma unroll
        for (int r = 0; r < 32; r++) {
            float a0 = __shfl_sync(0xffffffffu, attr[0], r);
            float a1 = __shfl_sync(0xffffffffu, attr[1], r);
            const float* wr = sW + r * 384 + lane;
            #pragma unroll
            for (int c = 0; c < 12; c++) {
                float wv = wr[32 * c];
                acc[0][c] = fmaf(a0, wv, acc[0][c]);
                acc[1][c] = fmaf(a1, wv, acc[1][c]);
            }
        }
        #pragma unroll
        for (int i = 0; i < 2; i++) {
            int e = e0 + i;
            if (e < E) {
                float* out = g_edp + (size_t)e * 384 + lane;
                #pragma unroll
                for (int c = 0; c < 12; c++) out[32 * c] = acc[i][c];
            }
        }
    }
}

// launch #5: gather + tensor-norm + layernorm(128)
__global__ void k_gather(const int* __restrict__ z,
                         const float* __restrict__ gam, const float* __restrict__ bet) {
    int n = blockIdx.x, h = threadIdx.x;
    __shared__ float red[4];

    int cnt = g_cnt[n];
    int off = g_off[n];
    int zn = z[n];
    float Un = g_U[(zn << 7) + h];

    float a = 0.f, bx = 0.f, by = 0.f, bz = 0.f;
    float xx = 0.f, yy = 0.f, zz = 0.f, xy = 0.f, xz = 0.f, yz = 0.f;

    for (int j = 0; j < cnt; j++) {
        int e = off + j;
        float4 rec = g_erec[e];
        int ezd = g_ez[e];
        bool selfe = (ezd < 0);
        int zdst = ezd & 127;
        float d = rec.w;
        float cut = 0.5f * (cosf(d * (float)PI_OVER_C) + 1.0f);
        float inv = selfe ? 1.0f : (1.0f / d);
        float vx = rec.x * inv, vy = rec.y * inv, vz = rec.z * inv;

        const float* dp = g_edp + (size_t)e * 384 + h;
        float d1 = dp[0], d2 = dp[128], d3 = dp[256];
        float C = cut * (Un + g_V[(zdst << 7) + h]);

        float ai = d1 * C, cb = d2 * C, cs = d3 * C;
        a  += ai;
        bx += cb * vx; by += cb * vy; bz += cb * vz;
        xx += cs * vx * vx; yy += cs * vy * vy; zz += cs * vz * vz;
        xy += cs * vx * vy; xz += cs * vx * vz; yz += cs * vy * vz;
    }

    int i = (n << 7) + h;
    float vals[10] = {a, bx, by, bz, xx, yy, zz, xy, xz, yz};
    #pragma unroll
    for (int p = 0; p < 10; p++) {
        bf16 hh, ll;
        split1(vals[p], hh, ll);
        g_accH[(size_t)p * (NN * 128) + i] = hh;
        g_accL[(size_t)p * (NN * 128) + i] = ll;
    }

    float tr = xx + yy + zz;
    float ms = xx * xx + yy * yy + zz * zz + 2.f * (xy * xy + xz * xz + yz * yz);
    float tn = 3.f * a * a + 2.f * (bx * bx + by * by + bz * bz) + ms - tr * tr * (1.f / 3.f);

    float v = tn;
    #pragma unroll
    for (int o = 16; o; o >>= 1) v += __shfl_xor_sync(0xffffffffu, v, o);
    if ((h & 31) == 0) red[h >> 5] = v;
    __syncthreads();
    float mean = (red[0] + red[1] + red[2] + red[3]) * (1.f / 128.f);
    float dev = tn - mean;
    v = dev * dev;
    #pragma unroll
    for (int o = 16; o; o >>= 1) v += __shfl_xor_sync(0xffffffffu, v, o);
    __syncthreads();
    if ((h & 31) == 0) red[h >> 5] = v;
    __syncthreads();
    float var = (red[0] + red[1] + red[2] + red[3]) * (1.f / 128.f);
    float T = dev * rsqrtf(var + 1e-5f) * gam[h] + bet[h];
    bf16 th, tl;
    split1(T, th, tl);
    g_TH[i] = th; g_TL[i] = tl;

    if (h == 0) { g_cnt[n] = 0; g_fill[n] = 0; }
}

// ---------------- combine + layernorm(384), fused ----------------
__global__ void k_combine_ln(const float* __restrict__ gam, const float* __restrict__ bet) {
    int n = blockIdx.x, k = threadIdx.x;
    int idx = (n << 7) + k;
    float Ip = g_mix[0][idx];
    float B0 = g_mix[1][idx], B1 = g_mix[2][idx], B2 = g_mix[3][idx];
    float xx = g_mix[4][idx], yy = g_mix[5][idx], zz = g_mix[6][idx];
    float xy = g_mix[7][idx], xz = g_mix[8][idx], yz = g_mix[9][idx];
    const float* nr = &g_NR[n * 384 + 3 * k];
    float n0 = nr[0], n1 = nr[1], n2 = nr[2];
    float t  = Ip * n0;
    float x0 = 3.f * t * t;
    float bb = B0 * B0 + B1 * B1 + B2 * B2;
    float x1 = 2.f * bb * n1 * n1;
    float tr = xx + yy + zz;
    float ms = xx * xx + yy * yy + zz * zz + 2.f * (xy * xy + xz * xz + yz * yz);
    float x2 = (ms - tr * tr * (1.f / 3.f)) * n2 * n2;

    __shared__ float red[4];
    float v = x0 + x1 + x2;
    #pragma unroll
    for (int o = 16; o; o >>= 1) v += __shfl_xor_sync(0xffffffffu, v, o);
    if ((k & 31) == 0) red[k >> 5] = v;
    __syncthreads();
    float mean = (red[0] + red[1] + red[2] + red[3]) * (1.f / 384.f);
    __syncthreads();
    float d0 = x0 - mean, d1 = x1 - mean, d2 = x2 - mean;
    v = d0 * d0 + d1 * d1 + d2 * d2;
    #pragma unroll
    for (int o = 16; o; o >>= 1) v += __shfl_xor_sync(0xffffffffu, v, o);
    if ((k & 31) == 0) red[k >> 5] = v;
    __syncthreads();
    float var = (red[0] + red[1] + red[2] + red[3]) * (1.f / 384.f);
    float rs = rsqrtf(var + 1e-5f);
    float o0 = d0 * rs * gam[k]       + bet[k];
    float o1 = d1 * rs * gam[128 + k] + bet[128 + k];
    float o2 = d2 * rs * gam[256 + k] + bet[256 + k];
    bf16 hh, ll;
    split1(o0, hh, ll); g_XNH[n * 384 + k]       = hh; g_XNL[n * 384 + k]       = ll;
    split1(o1, hh, ll); g_XNH[n * 384 + 128 + k] = hh; g_XNL[n * 384 + 128 + k] = ll;
    split1(o2, hh, ll); g_XNH[n * 384 + 256 + k] = hh; g_XNL[n * 384 + 256 + k] = ll;
}

// ---------------- launch ----------------
extern "C" void kernel_launch(void* const* d_in, const int* in_sizes, int n_in,
                              void* d_out, int out_size) {
    const int*   z      = (const int*)d_in[0];
    const float* pos    = (const float*)d_in[1];
    const int*   ei     = (const int*)d_in[3];
    const float* emb_w  = (const float*)d_in[4];
    const float* emb2_w = (const float*)d_in[5];
    const float* emb2_b = (const float*)d_in[6];
    const float* dp1w   = (const float*)d_in[7];
    const float* dp1b   = (const float*)d_in[8];
    const float* dp2w   = (const float*)d_in[9];
    const float* dp2b   = (const float*)d_in[10];
    const float* dp3w   = (const float*)d_in[11];
    const float* dp3b   = (const float*)d_in[12];
    const float* lt0w   = (const float*)d_in[13];
    const float* lt1w   = (const float*)d_in[14];
    const float* lt2w   = (const float*)d_in[15];
    const float* ls0w   = (const float*)d_in[16];
    const float* ls0b   = (const float*)d_in[17];
    const float* ls1w   = (const float*)d_in[18];
    const float* ls1b   = (const float*)d_in[19];
    const float* ing    = (const float*)d_in[20];
    const float* inb    = (const float*)d_in[21];
    const float* linw   = (const float*)d_in[22];
    const float* linb   = (const float*)d_in[23];
    const float* ong    = (const float*)d_in[24];
    const float* onb    = (const float*)d_in[25];
    const float* ol1w   = (const float*)d_in[26];
    const float* ol1b   = (const float*)d_in[27];
    const float* ol2w   = (const float*)d_in[28];
    const float* ol2b   = (const float*)d_in[29];
    float* y = (float*)d_out;

    cudaFuncSetAttribute(tg_mixls0, cudaFuncAttributeMaxDynamicSharedMemorySize, TG_SMEM);
    cudaFuncSetAttribute(tg_ls1, cudaFuncAttributeMaxDynamicSharedMemorySize, TG_SMEM);
    cudaFuncSetAttribute(tg_tail, cudaFuncAttributeMaxDynamicSharedMemorySize, TG_SMEM);
    cudaFuncSetAttribute(k_edgedp, cudaFuncAttributeMaxDynamicSharedMemorySize, EDP_SMEM);

    k_count<<<368, 256>>>(ei, pos, emb_w, emb2_w, emb2_b,
                          dp1w, dp1b, dp2w, dp2b, dp3w, dp3b);
    k_scan<<<1, 1024>>>();
    k_scatter<<<NE / 256, 256>>>(ei, pos, z);
    k_edgedp<<<EDP_BLOCKS, 256, EDP_SMEM>>>();
    k_gather<<<NN, 128>>>(z, ing, inb);
    k_wprep<<<928, 256>>>(ls0w, ls1w, linw, lt0w, lt1w, lt2w, ol1w);
    tg_mixls0<<<1536, 256, TG_SMEM>>>(ls0b);
    tg_ls1<<<dim3(NN / 128, 3), 256, TG_SMEM>>>(ls1b);
    k_combine_ln<<<NN, 128>>>(ong, onb);
    tg_tail<<<NN / 128, 256, TG_SMEM>>>(linb, ol1b, ol2w, ol2b, y);
}

// round 16
// speedup vs baseline: 1.0213x; 1.0050x over previous
#include <cuda_runtime.h>
#include <cuda_bf16.h>
#include <math.h>
#include <stdint.h>

#define NN 16384
#define NE 65536
typedef __nv_bfloat16 bf16;

// ---------------- fp32 scratch ----------------
static __device__ __align__(256) float g_U[128 * 128];
static __device__ __align__(256) float g_V[128 * 128];
static __device__ __align__(256) float g_NR[NN * 384];
static __device__ __align__(256) float g_mix[10][NN * 128];
static __device__ __align__(256) float g_Wt[32 * 384];
static __device__ __align__(256) float g_db[384];
static __device__ __align__(256) float g_edp[(size_t)NE * 384];
static __device__ int g_Etot;

// ---------------- bf16 hi/lo activations ----------------
static __device__ __align__(256) bf16 g_accH[10 * NN * 128], g_accL[10 * NN * 128];
static __device__ __align__(256) bf16 g_TH[NN * 128],  g_TL[NN * 128];
static __device__ __align__(256) bf16 g_H1H[NN * 256], g_H1L[NN * 256];
static __device__ __align__(256) bf16 g_XNH[NN * 384], g_XNL[NN * 384];

// ---------------- bf16 hi/lo weights ----------------
static __device__ __align__(256) bf16 w_ls0H[256 * 128], w_ls0L[256 * 128];
static __device__ __align__(256) bf16 w_ls1H[384 * 256], w_ls1L[384 * 256];
static __device__ __align__(256) bf16 w_linH[128 * 384], w_linL[128 * 384];
static __device__ __align__(256) bf16 w_ltH[3 * 128 * 128], w_ltL[3 * 128 * 128];
static __device__ __align__(256) bf16 w_ol1H[64 * 128], w_ol1L[64 * 128];

// ---------------- CSR edge compaction ----------------
static __device__ __align__(256) int    g_cnt[NN];
static __device__ __align__(256) int    g_off[NN];
static __device__ __align__(256) int    g_fill[NN];
static __device__ __align__(256) float4 g_erec[NE];
static __device__ __align__(256) int    g_ez[NE];

__device__ __forceinline__ float silu(float x) { return x / (1.f + expf(-x)); }
__device__ __forceinline__ void split1(float v, bf16& h, bf16& l) {
    h = __float2bfloat16(v);
    l = __float2bfloat16(v - __bfloat162float(h));
}

#define RBF_START 0.011108996538242306
#define RBF_BETA  (1.0 / ((0.0625 * (1.0 - RBF_START)) * (0.0625 * (1.0 - RBF_START))))
#define RBF_ALPHA (5.0 / 4.5)
#define PI_OVER_C 0.6981317007977318

// =================== MMA plumbing ===================
__device__ __forceinline__ uint32_t smem_u32(const void* p) {
    uint32_t a;
    asm("{ .reg .u64 t; cvta.to.shared.u64 t, %1; cvt.u32.u64 %0, t; }" : "=r"(a) : "l"(p));
    return a;
}
__device__ __forceinline__ void ldm_x4(uint32_t addr, uint32_t* r) {
    asm volatile("ldmatrix.sync.aligned.m8n8.x4.shared.b16 {%0,%1,%2,%3}, [%4];"
                 : "=r"(r[0]), "=r"(r[1]), "=r"(r[2]), "=r"(r[3]) : "r"(addr));
}
__device__ __forceinline__ void mma16816(float* c, const uint32_t* a, const uint32_t* b) {
    asm volatile("mma.sync.aligned.m16n8k16.row.col.f32.bf16.bf16.f32 "
                 "{%0,%1,%2,%3}, {%4,%5,%6,%7}, {%8,%9}, {%0,%1,%2,%3};"
                 : "+f"(c[0]), "+f"(c[1]), "+f"(c[2]), "+f"(c[3])
                 : "r"(a[0]), "r"(a[1]), "r"(a[2]), "r"(a[3]), "r"(b[0]), "r"(b[1]));
}
__device__ __forceinline__ void cpa16(uint32_t s, const void* g) {
    asm volatile("cp.async.cg.shared.global [%0], [%1], 16;" :: "r"(s), "l"(g));
}
#define CP_COMMIT() asm volatile("cp.async.commit_group;")
#define CP_WAIT0()  asm volatile("cp.async.wait_group 0;" ::: "memory")

#define TPAD 136
#define SM_A (128 * TPAD * 2)
#define SM_W (64 * TPAD * 2)
#define TG_SMEM (2 * SM_A + 2 * SM_W)   // 104448 -> 2 CTAs/SM

template <int OUT, int FT>
__device__ __forceinline__ void mma_gemm_bf(
    int bx, int by,
    const bf16* __restrict__ AH, const bf16* __restrict__ AL,
    const bf16* __restrict__ WH, const bf16* __restrict__ WL,
    const float* __restrict__ bias,
    float* __restrict__ C, bf16* __restrict__ CH, bf16* __restrict__ CL,
    int K, int F, bool act) {
    extern __shared__ __align__(16) char smem[];
    const uint32_t aH_u = smem_u32(smem);
    const uint32_t aL_u = aH_u + SM_A;
    const uint32_t wH_u = aH_u + 2 * SM_A;
    const uint32_t wL_u = wH_u + SM_W;

    const int tid = threadIdx.x, lane = tid & 31, wid = tid >> 5;
    const int wm = wid & 3, wn = wid >> 2;
    const int m0 = bx << 7;
    const int f0 = by * (64 * FT);

    float c[FT][2][4][4];
    #pragma unroll
    for (int ft = 0; ft < FT; ft++)
        #pragma unroll
        for (int i = 0; i < 2; i++)
            #pragma unroll
            for (int j = 0; j < 4; j++)
                #pragma unroll
                for (int q = 0; q < 4; q++) c[ft][i][j][q] = 0.f;

    const int a_row = wm * 32 + (lane & 15);
    const int a_col = (lane >> 4) << 3;
    const int b_row = wn * 32 + (lane & 7) + ((lane >> 4) << 3);
    const int b_col = ((lane >> 3) & 1) << 3;

    for (int kc = 0; kc < K; kc += 128) {
        __syncthreads();
        #pragma unroll
        for (int i = tid; i < 2048; i += 256) {
            int r = i >> 4, c8 = (i & 15) << 3;
            uint32_t so = (uint32_t)(r * TPAD + c8) * 2;
            size_t go = (size_t)(m0 + r) * K + kc + c8;
            cpa16(aH_u + so, AH + go);
            cpa16(aL_u + so, AL + go);
        }
        #pragma unroll
        for (int i = tid; i < 1024; i += 256) {
            int r = i >> 4, c8 = (i & 15) << 3;
            uint32_t so = (uint32_t)(r * TPAD + c8) * 2;
            size_t go = (size_t)(f0 + r) * K + kc + c8;
            cpa16(wH_u + so, WH + go);
            cpa16(wL_u + so, WL + go);
        }
        CP_COMMIT();
        CP_WAIT0();
        __syncthreads();

        #pragma unroll
        for (int ft = 0; ft < FT; ft++) {
            if (ft > 0) {
                __syncthreads();
                #pragma unroll
                for (int i = tid; i < 1024; i += 256) {
                    int r = i >> 4, c8 = (i & 15) << 3;
                    uint32_t so = (uint32_t)(r * TPAD + c8) * 2;
                    size_t go = (size_t)(f0 + ft * 64 + r) * K + kc + c8;
                    cpa16(wH_u + so, WH + go);
                    cpa16(wL_u + so, WL + go);
                }
                CP_COMMIT();
                CP_WAIT0();
                __syncthreads();
            }
            #pragma unroll
            for (int ks = 0; ks < 8; ks++) {
                uint32_t ah[2][4], al[2][4];
                #pragma unroll
                for (int mf = 0; mf < 2; mf++) {
                    uint32_t off = (uint32_t)((a_row + mf * 16) * TPAD + a_col + ks * 16) * 2;
                    ldm_x4(aH_u + off, ah[mf]);
                    ldm_x4(aL_u + off, al[mf]);
                }
                #pragma unroll
                for (int nfp = 0; nfp < 2; nfp++) {
                    uint32_t boff = (uint32_t)((b_row + nfp * 16) * TPAD + b_col + ks * 16) * 2;
                    uint32_t bh[4], bl[4];
                    ldm_x4(wH_u + boff, bh);
                    ldm_x4(wL_u + boff, bl);
                    #pragma unroll
                    for (int mf = 0; mf < 2; mf++) {
                        mma16816(c[ft][mf][2 * nfp], ah[mf], bh);
                        mma16816(c[ft][mf][2 * nfp], ah[mf], bl);
                        mma16816(c[ft][mf][2 * nfp], al[mf], bh);
                        mma16816(c[ft][mf][2 * nfp + 1], ah[mf], bh + 2);
                        mma16816(c[ft][mf][2 * nfp + 1], ah[mf], bl + 2);
                        mma16816(c[ft][mf][2 * nfp + 1], al[mf], bh + 2);
                    }
                }
            }
        }
    }

    #pragma unroll
    for (int ft = 0; ft < FT; ft++) {
        #pragma unroll
        for (int mf = 0; mf < 2; mf++) {
            #pragma unroll
            for (int nf = 0; nf < 4; nf++) {
                int grow = m0 + wm * 32 + mf * 16 + (lane >> 2);
                int gcol = f0 + ft * 64 + wn * 32 + nf * 8 + ((lane & 3) << 1);
                float b0 = bias ? bias[gcol] : 0.f;
                float b1 = bias ? bias[gcol + 1] : 0.f;
                float v0 = c[ft][mf][nf][0] + b0, v1 = c[ft][mf][nf][1] + b1;
                float v2 = c[ft][mf][nf][2] + b0, v3 = c[ft][mf][nf][3] + b1;
                if (act) { v0 = silu(v0); v1 = silu(v1); v2 = silu(v2); v3 = silu(v3); }
                if (OUT == 0) {
                    *(float2*)&C[(size_t)grow * F + gcol] = make_float2(v0, v1);
                    *(float2*)&C[(size_t)(grow + 8) * F + gcol] = make_float2(v2, v3);
                } else {
                    bf16 h0, l0, h1, l1;
                    split1(v0, h0, l0); split1(v1, h1, l1);
                    *(__nv_bfloat162*)&CH[(size_t)grow * F + gcol] = __halves2bfloat162(h0, h1);
                    *(__nv_bfloat162*)&CL[(size_t)grow * F + gcol] = __halves2bfloat162(l0, l1);
                    split1(v2, h0, l0); split1(v3, h1, l1);
                    *(__nv_bfloat162*)&CH[(size_t)(grow + 8) * F + gcol] = __halves2bfloat162(h0, h1);
                    *(__nv_bfloat162*)&CL[(size_t)(grow + 8) * F + gcol] = __halves2bfloat162(l0, l1);
                }
            }
        }
    }
}

__global__ __launch_bounds__(256, 2)
void tg_mixls0(const float* __restrict__ ls0b) {
    int bid = blockIdx.x;
    if (bid < 1280) {
        int plane = bid >> 7;
        int sel = (plane == 0) ? 0 : (plane < 4 ? 1 : 2);
        mma_gemm_bf<0, 2>(bid, 0, g_accH, g_accL, w_ltH + sel * 16384, w_ltL + sel * 16384,
                          nullptr, &g_mix[0][0], nullptr, nullptr, 128, 128, false);
    } else {
        int b = bid - 1280;
        mma_gemm_bf<1, 2>(b & 127, b >> 7, g_TH, g_TL, w_ls0H, w_ls0L, ls0b,
                          nullptr, g_H1H, g_H1L, 128, 256, true);
    }
}
__global__ __launch_bounds__(256, 2)
void tg_ls1(const float* __restrict__ b) {
    mma_gemm_bf<0, 2>(blockIdx.x, blockIdx.y, g_H1H, g_H1L, w_ls1H, w_ls1L, b,
                      g_NR, nullptr, nullptr, 256, 384, true);
}

// =================== fused tail: lin GEMM -> ol1 GEMM -> final dot ===================
__global__ __launch_bounds__(256, 2)
void tg_tail(const float* __restrict__ linb, const float* __restrict__ ol1b,
             const float* __restrict__ ol2w, const float* __restrict__ ol2b,
             float* __restrict__ y) {
    extern __shared__ __align__(16) char smem[];
    const uint32_t aH_u = smem_u32(smem);
    const uint32_t aL_u = aH_u + SM_A;
    const uint32_t wH_u = aH_u + 2 * SM_A;
    const uint32_t wL_u = wH_u + SM_W;
    __shared__ float ypart[128];

    const int tid = threadIdx.x, lane = tid & 31, wid = tid >> 5;
    const int wm = wid & 3, wn = wid >> 2;
    const int m0 = blockIdx.x << 7;

    const int a_row = wm * 32 + (lane & 15);
    const int a_col = (lane >> 4) << 3;
    const int b_row = wn * 32 + (lane & 7) + ((lane >> 4) << 3);
    const int b_col = ((lane >> 3) & 1) << 3;

    float c[2][2][4][4];
    #pragma unroll
    for (int ft = 0; ft < 2; ft++)
        #pragma unroll
        for (int i = 0; i < 2; i++)
            #pragma unroll
            for (int j = 0; j < 4; j++)
                #pragma unroll
                for (int q = 0; q < 4; q++) c[ft][i][j][q] = 0.f;

    for (int kc = 0; kc < 384; kc += 128) {
        __syncthreads();
        #pragma unroll
        for (int i = tid; i < 2048; i += 256) {
            int r = i >> 4, c8 = (i & 15) << 3;
            uint32_t so = (uint32_t)(r * TPAD + c8) * 2;
            size_t go = (size_t)(m0 + r) * 384 + kc + c8;
            cpa16(aH_u + so, g_XNH + go);
            cpa16(aL_u + so, g_XNL + go);
        }
        #pragma unroll
        for (int i = tid; i < 1024; i += 256) {
            int r = i >> 4, c8 = (i & 15) << 3;
            uint32_t so = (uint32_t)(r * TPAD + c8) * 2;
            size_t go = (size_t)r * 384 + kc + c8;
            cpa16(wH_u + so, w_linH + go);
            cpa16(wL_u + so, w_linL + go);
        }
        CP_COMMIT();
        CP_WAIT0();
        __syncthreads();

        #pragma unroll
        for (int ft = 0; ft < 2; ft++) {
            if (ft > 0) {
                __syncthreads();
                #pragma unroll
                for (int i = tid; i < 1024; i += 256) {
                    int r = i >> 4, c8 = (i & 15) << 3;
                    uint32_t so = (uint32_t)(r * TPAD + c8) * 2;
                    size_t go = (size_t)(64 + r) * 384 + kc + c8;
                    cpa16(wH_u + so, w_linH + go);
                    cpa16(wL_u + so, w_linL + go);
                }
                CP_COMMIT();
                CP_WAIT0();
                __syncthreads();
            }
            #pragma unroll
            for (int ks = 0; ks < 8; ks++) {
                uint32_t ah[2][4], al[2][4];
                #pragma unroll
                for (int mf = 0; mf < 2; mf++) {
                    uint32_t off = (uint32_t)((a_row + mf * 16) * TPAD + a_col + ks * 16) * 2;
                    ldm_x4(aH_u + off, ah[mf]);
                    ldm_x4(aL_u + off, al[mf]);
                }
                #pragma unroll
                for (int nfp = 0; nfp < 2; nfp++) {
                    uint32_t boff = (uint32_t)((b_row + nfp * 16) * TPAD + b_col + ks * 16) * 2;
                    uint32_t bh[4], bl[4];
                    ldm_x4(wH_u + boff, bh);
                    ldm_x4(wL_u + boff, bl);
                    #pragma unroll
                    for (int mf = 0; mf < 2; mf++) {
                        mma16816(c[ft][mf][2 * nfp], ah[mf], bh);
                        mma16816(c[ft][mf][2 * nfp], ah[mf], bl);
                        mma16816(c[ft][mf][2 * nfp], al[mf], bh);
                        mma16816(c[ft][mf][2 * nfp + 1], ah[mf], bh + 2);
                        mma16816(c[ft][mf][2 * nfp + 1], ah[mf], bl + 2);
                        mma16816(c[ft][mf][2 * nfp + 1], al[mf], bh + 2);
                    }
                }
            }
        }
    }

    __syncthreads();
    #pragma unroll
    for (int ft = 0; ft < 2; ft++) {
        #pragma unroll
        for (int mf = 0; mf < 2; mf++) {
            #pragma unroll
            for (int nf = 0; nf < 4; nf++) {
                int lrow = wm * 32 + mf * 16 + (lane >> 2);
                int lcol = ft * 64 + wn * 32 + nf * 8 + ((lane & 3) << 1);
                float b0 = linb[lcol], b1 = linb[lcol + 1];
                float v0 = silu(c[ft][mf][nf][0] + b0);
                float v1 = silu(c[ft][mf][nf][1] + b1);
                float v2 = silu(c[ft][mf][nf][2] + b0);
                float v3 = silu(c[ft][mf][nf][3] + b1);
                bf16 h0, l0, h1, l1;
                split1(v0, h0, l0); split1(v1, h1, l1);
                *(__nv_bfloat162*)(smem + (size_t)(lrow * TPAD + lcol) * 2) =
                    __halves2bfloat162(h0, h1);
                *(__nv_bfloat162*)(smem + SM_A + (size_t)(lrow * TPAD + lcol) * 2) =
                    __halves2bfloat162(l0, l1);
                split1(v2, h0, l0); split1(v3, h1, l1);
                *(__nv_bfloat162*)(smem + (size_t)((lrow + 8) * TPAD + lcol) * 2) =
                    __halves2bfloat162(h0, h1);
                *(__nv_bfloat162*)(smem + SM_A + (size_t)((lrow + 8) * TPAD + lcol) * 2) =
                    __halves2bfloat162(l0, l1);
            }
        }
    }
    #pragma unroll
    for (int i = tid; i < 1024; i += 256) {
        int r = i >> 4, c8 = (i & 15) << 3;
        if (r < 64) {
            uint32_t so = (uint32_t)(r * TPAD + c8) * 2;
            cpa16(wH_u + so, w_ol1H + r * 128 + c8);
            cpa16(wL_u + so, w_ol1L + r * 128 + c8);
        }
    }
    CP_COMMIT();
    CP_WAIT0();
    if (tid < 128) ypart[tid] = 0.f;
    __syncthreads();

    float c2[2][4][4];
    #pragma unroll
    for (int i = 0; i < 2; i++)
        #pragma unroll
        for (int j = 0; j < 4; j++)
            #pragma unroll
            for (int q = 0; q < 4; q++) c2[i][j][q] = 0.f;

    #pragma unroll
    for (int ks = 0; ks < 8; ks++) {
        uint32_t ah[2][4], al[2][4];
        #pragma unroll
        for (int mf = 0; mf < 2; mf++) {
            uint32_t off = (uint32_t)((a_row + mf * 16) * TPAD + a_col + ks * 16) * 2;
            ldm_x4(aH_u + off, ah[mf]);
            ldm_x4(aL_u + off, al[mf]);
        }
        #pragma unroll
        for (int nfp = 0; nfp < 2; nfp++) {
            uint32_t boff = (uint32_t)((b_row + nfp * 16) * TPAD + b_col + ks * 16) * 2;
            uint32_t bh[4], bl[4];
            ldm_x4(wH_u + boff, bh);
            ldm_x4(wL_u + boff, bl);
            #pragma unroll
            for (int mf = 0; mf < 2; mf++) {
                mma16816(c2[mf][2 * nfp], ah[mf], bh);
                mma16816(c2[mf][2 * nfp], ah[mf], bl);
                mma16816(c2[mf][2 * nfp], al[mf], bh);
                mma16816(c2[mf][2 * nfp + 1], ah[mf], bh + 2);
                mma16816(c2[mf][2 * nfp + 1], ah[mf], bl + 2);
                mma16816(c2[mf][2 * nfp + 1], al[mf], bh + 2);
            }
        }
    }

    #pragma unroll
    for (int mf = 0; mf < 2; mf++) {
        float pr0 = 0.f, pr8 = 0.f;
        #pragma unroll
        for (int nf = 0; nf < 4; nf++) {
            int gcol = wn * 32 + nf * 8 + ((lane & 3) << 1);
            float b0 = ol1b[gcol], b1 = ol1b[gcol + 1];
            float w0 = ol2w[gcol], w1 = ol2w[gcol + 1];
            pr0 += silu(c2[mf][nf][0] + b0) * w0 + silu(c2[mf][nf][1] + b1) * w1;
            pr8 += silu(c2[mf][nf][2] + b0) * w0 + silu(c2[mf][nf][3] + b1) * w1;
        }
        int lrow = wm * 32 + mf * 16 + (lane >> 2);
        atomicAdd(&ypart[lrow], pr0);
        atomicAdd(&ypart[lrow + 8], pr8);
    }
    __syncthreads();
    if (tid < 128) y[m0 + tid] = ypart[tid] + ol2b[0];
}

// ---------------- weight pre-split ----------------
__global__ void k_wprep(const float* __restrict__ ls0w, const float* __restrict__ ls1w,
                        const float* __restrict__ linw, const float* __restrict__ lt0w,
                        const float* __restrict__ lt1w, const float* __restrict__ lt2w,
                        const float* __restrict__ ol1w) {
    int j = blockIdx.x * 256 + threadIdx.x;
    const float* src; bf16 *dh, *dl;
    if (j < 32768) { src = ls0w; dh = w_ls0H; dl = w_ls0L; }
    else if ((j -= 32768) < 98304) { src = ls1w; dh = w_ls1H; dl = w_ls1L; }
    else if ((j -= 98304) < 49152) { src = linw; dh = w_linH; dl = w_linL; }
    else if ((j -= 49152) < 16384) { src = lt0w; dh = w_ltH; dl = w_ltL; }
    else if ((j -= 16384) < 16384) { src = lt1w; dh = w_ltH + 16384; dl = w_ltL + 16384; }
    else if ((j -= 16384) < 16384) { src = lt2w; dh = w_ltH + 32768; dl = w_ltL + 32768; }
    else if ((j -= 16384) < 8192)  { src = ol1w; dh = w_ol1H; dl = w_ol1L; }
    else return;
    bf16 h, l;
    split1(src[j], h, l);
    dh[j] = h; dl[j] = l;
}

// =================== launch #1: edge count + U/V tables + dp transpose ===================
__global__ void k_count(const int* __restrict__ ei, const float* __restrict__ pos,
                        const float* __restrict__ emb_w, const float* __restrict__ emb2_w,
                        const float* __restrict__ emb2_b,
                        const float* __restrict__ dp1w, const float* __restrict__ dp1b,
                        const float* __restrict__ dp2w, const float* __restrict__ dp2b,
                        const float* __restrict__ dp3w, const float* __restrict__ dp3b) {
    int b = blockIdx.x;
    if (b < 256) {
        int e = b * 256 + threadIdx.x;
        int src = ei[e], dst = ei[NE + e];
        float vx = pos[src * 3 + 0] - pos[dst * 3 + 0];
        float vy = pos[src * 3 + 1] - pos[dst * 3 + 1];
        float vz = pos[src * 3 + 2] - pos[dst * 3 + 2];
        float d = sqrtf(vx * vx + vy * vy + vz * vz);
        if (src == dst || d < 4.5f) atomicAdd(&g_cnt[src], 1);
    } else if (b < 320) {
        int zt = ((b - 256) << 1) | (threadIdx.x >> 7);
        int h = threadIdx.x & 127;
        float u = emb2_b[h];
        float v = 0.f;
        #pragma unroll 4
        for (int k = 0; k < 128; k++) {
            float e = emb_w[zt * 128 + k];
            u = fmaf(e, emb2_w[h * 256 + k], u);
            v = fmaf(e, emb2_w[h * 256 + 128 + k], v);
        }
        g_U[zt * 128 + h] = u;
        g_V[zt * 128 + h] = v;
    } else {
        int j = (b - 320) * 256 + threadIdx.x;
        int r = j / 384, col = j - r * 384;
        float v = col < 128 ? dp1w[col * 32 + r]
                : col < 256 ? dp2w[(col - 128) * 32 + r]
                            : dp3w[(col - 256) * 32 + r];
        g_Wt[j] = v;
        if (j < 384)
            g_db[j] = j < 128 ? dp1b[j] : j < 256 ? dp2b[j - 128] : dp3b[j - 256];
    }
}

// launch #2: exclusive scan + total edge count
__global__ void k_scan() {
    __shared__ int ws[32];
    int t = threadIdx.x;
    int lane = t & 31, w = t >> 5;
    int base = t * 16;
    int4 v0 = *(int4*)&g_cnt[base];
    int4 v1 = *(int4*)&g_cnt[base + 4];
    int4 v2 = *(int4*)&g_cnt[base + 8];
    int4 v3 = *(int4*)&g_cnt[base + 12];
    int cv[16] = {v0.x, v0.y, v0.z, v0.w, v1.x, v1.y, v1.z, v1.w,
                  v2.x, v2.y, v2.z, v2.w, v3.x, v3.y, v3.z, v3.w};
    int local[16];
    int s = 0;
    #pragma unroll
    for (int i = 0; i < 16; i++) { local[i] = s; s += cv[i]; }
    int inc = s;
    #pragma unroll
    for (int off = 1; off < 32; off <<= 1) {
        int x = __shfl_up_sync(0xffffffffu, inc, off);
        if (lane >= off) inc += x;
    }
    if (lane == 31) ws[w] = inc;
    __syncthreads();
    if (w == 0) {
        int wi = ws[lane];
        #pragma unroll
        for (int off = 1; off < 32; off <<= 1) {
            int x = __shfl_up_sync(0xffffffffu, wi, off);
            if (lane >= off) wi += x;
        }
        ws[lane] = wi;
    }
    __syncthreads();
    int warp_pre = (w == 0) ? 0 : ws[w - 1];
    int pre = warp_pre + inc - s;
    int4 o0 = make_int4(pre + local[0], pre + local[1], pre + local[2], pre + local[3]);
    int4 o1 = make_int4(pre + local[4], pre + local[5], pre + local[6], pre + local[7]);
    int4 o2 = make_int4(pre + local[8], pre + local[9], pre + local[10], pre + local[11]);
    int4 o3 = make_int4(pre + local[12], pre + local[13], pre + local[14], pre + local[15]);
    *(int4*)&g_off[base] = o0;
    *(int4*)&g_off[base + 4] = o1;
    *(int4*)&g_off[base + 8] = o2;
    *(int4*)&g_off[base + 12] = o3;
    if (t == 1023) g_Etot = pre + local[15] + cv[15];
}

// launch #3
__global__ void k_scatter(const int* __restrict__ ei, const float* __restrict__ pos,
                          const int* __restrict__ z) {
    int e = blockIdx.x * 256 + threadIdx.x;
    if (e >= NE) return;
    int src = ei[e], dst = ei[NE + e];
    float vx = pos[src * 3 + 0] - pos[dst * 3 + 0];
    float vy = pos[src * 3 + 1] - pos[dst * 3 + 1];
    float vz = pos[src * 3 + 2] - pos[dst * 3 + 2];
    float d = sqrtf(vx * vx + vy * vy + vz * vz);
    bool selfe = (src == dst);
    if (!selfe && !(d < 4.5f)) return;
    int slot = g_off[src] + atomicAdd(&g_fill[src], 1);
    g_erec[slot] = make_float4(vx, vy, vz, d);
    g_ez[slot] = z[dst] | (selfe ? (int)0x80000000 : 0);
}

// launch #4: per-edge dp projections.
// 4 edges per warp iteration, channels split into 2 passes of 6 (24 acc regs).
#define EDP_SMEM ((32 * 384 + 384) * 4)
#define EDP_BLOCKS 444
__global__ __launch_bounds__(256, 3)
void k_edgedp() {
    extern __shared__ float sdp[];
    float* sW = sdp;
    float* sb = sdp + 32 * 384;
    int tid = threadIdx.x;

    #pragma unroll 8
    for (int i = tid; i < 32 * 384; i += 256) sW[i] = g_Wt[i];
    if (tid < 128) {
        sb[tid] = g_db[tid];
        sb[128 + tid] = g_db[128 + tid];
        sb[256 + tid] = g_db[256 + tid];
    }
    __syncthreads();

    int E = g_Etot;
    int lane = tid & 31, w = tid >> 5;
    float mean = (float)RBF_START + (float)lane * (float)((1.0 - RBF_START) / 31.0);

    int gw = blockIdx.x * 8 + w;
    int nw = EDP_BLOCKS * 8;
    for (int e0 = gw * 4; e0 < E; e0 += nw * 4) {
        float attr[4];
        #pragma unroll
        for (int i = 0; i < 4; i++) {
            int e = e0 + i;
            if (e < E) {
                float d = g_erec[e].w;
                float cut = 0.5f * (cosf(d * (float)PI_OVER_C) + 1.0f);
                float gex = expf(-(float)RBF_ALPHA * d);
                float diff = gex - mean;
                attr[i] = cut * expf(-(float)RBF_BETA * diff * diff);
            } else attr[i] = 0.f;
        }

        #pragma unroll
        for (int half = 0; half < 2; half++) {
            float acc[4][6];
            #pragma unroll
            for (int i = 0; i < 4; i++)
                #pragma unroll
                for (int c = 0; c < 6; c++)
                    acc[i][c] = sb[lane + 32 * (half * 6 + c)];

            #pragma unroll
            for (int r = 0; r < 32; r++) {
                float a0 = __shfl_sync(0xffffffffu, attr[0], r);
                float a1 = __shfl_sync(0xffffffffu, attr[1], r);
                float a2 = __shfl_sync(0xffffffffu, attr[2], r);
                float a3 = __shfl_sync(0xffffffffu, attr[3], r);
                const float* wr = sW + r * 384 + lane + half * 192;
                #pragma unroll
                for (int c = 0; c < 6; c++) {
                    float wv = wr[32 * c];
                    acc[0][c] = fmaf(a0, wv, acc[0][c]);
                    acc[1][c] = fmaf(a1, wv, acc[1][c]);
                    acc[2][c] = fmaf(a2, wv, acc[2][c]);
                    acc[3][c] = fmaf(a3, wv, acc[3][c]);
                }
            }
            #pragma unroll
            for (int i = 0; i < 4; i++) {
                int e = e0 + i;
                if (e < E) {
                    float* out = g_edp + (size_t)e * 384 + lane + half * 192;
                    #pragma unroll
                    for (int c = 0; c < 6; c++) out[32 * c] = acc[i][c];
                }
            }
        }
    }
}

// launch #5: gather + tensor-norm + layernorm(128)
__global__ void k_gather(const int* __restrict__ z,
                         const float* __restrict__ gam, const float* __restrict__ bet) {
    int n = blockIdx.x, h = threadIdx.x;
    __shared__ float red[4];

    int cnt = g_cnt[n];
    int off = g_off[n];
    int zn = z[n];
    float Un = g_U[(zn << 7) + h];

    float a = 0.f, bx = 0.f, by = 0.f, bz = 0.f;
    float xx = 0.f, yy = 0.f, zz = 0.f, xy = 0.f, xz = 0.f, yz = 0.f;

    for (int j = 0; j < cnt; j++) {
        int e = off + j;
        float4 rec = g_erec[e];
        int ezd = g_ez[e];
        bool selfe = (ezd < 0);
        int zdst = ezd & 127;
        float d = rec.w;
        float cut = 0.5f * (cosf(d * (float)PI_OVER_C) + 1.0f);
        float inv = selfe ? 1.0f : (1.0f / d);
        float vx = rec.x * inv, vy = rec.y * inv, vz = rec.z * inv;

        const float* dp = g_edp + (size_t)e * 384 + h;
        float d1 = dp[0], d2 = dp[128], d3 = dp[256];
        float C = cut * (Un + g_V[(zdst << 7) + h]);

        float ai = d1 * C, cb = d2 * C, cs = d3 * C;
        a  += ai;
        bx += cb * vx; by += cb * vy; bz += cb * vz;
        xx += cs * vx * vx; yy += cs * vy * vy; zz += cs * vz * vz;
        xy += cs * vx * vy; xz += cs * vx * vz; yz += cs * vy * vz;
    }

    int i = (n << 7) + h;
    float vals[10] = {a, bx, by, bz, xx, yy, zz, xy, xz, yz};
    #pragma unroll
    for (int p = 0; p < 10; p++) {
        bf16 hh, ll;
        split1(vals[p], hh, ll);
        g_accH[(size_t)p * (NN * 128) + i] = hh;
        g_accL[(size_t)p * (NN * 128) + i] = ll;
    }

    float tr = xx + yy + zz;
    float ms = xx * xx + yy * yy + zz * zz + 2.f * (xy * xy + xz * xz + yz * yz);
    float tn = 3.f * a * a + 2.f * (bx * bx + by * by + bz * bz) + ms - tr * tr * (1.f / 3.f);

    float v = tn;
    #pragma unroll
    for (int o = 16; o; o >>= 1) v += __shfl_xor_sync(0xffffffffu, v, o);
    if ((h & 31) == 0) red[h >> 5] = v;
    __syncthreads();
    float mean = (red[0] + red[1] + red[2] + red[3]) * (1.f / 128.f);
    float dev = tn - mean;
    v = dev * dev;
    #pragma unroll
    for (int o = 16; o; o >>= 1) v += __shfl_xor_sync(0xffffffffu, v, o);
    __syncthreads();
    if ((h & 31) == 0) red[h >> 5] = v;
    __syncthreads();
    float var = (red[0] + red[1] + red[2] + red[3]) * (1.f / 128.f);
    float T = dev * rsqrtf(var + 1e-5f) * gam[h] + bet[h];
    bf16 th, tl;
    split1(T, th, tl);
    g_TH[i] = th; g_TL[i] = tl;

    if (h == 0) { g_cnt[n] = 0; g_fill[n] = 0; }
}

// ---------------- combine + layernorm(384), fused ----------------
__global__ void k_combine_ln(const float* __restrict__ gam, const float* __restrict__ bet) {
    int n = blockIdx.x, k = threadIdx.x;
    int idx = (n << 7) + k;
    float Ip = g_mix[0][idx];
    float B0 = g_mix[1][idx], B1 = g_mix[2][idx], B2 = g_mix[3][idx];
    float xx = g_mix[4][idx], yy = g_mix[5][idx], zz = g_mix[6][idx];
    float xy = g_mix[7][idx], xz = g_mix[8][idx], yz = g_mix[9][idx];
    const float* nr = &g_NR[n * 384 + 3 * k];
    float n0 = nr[0], n1 = nr[1], n2 = nr[2];
    float t  = Ip * n0;
    float x0 = 3.f * t * t;
    float bb = B0 * B0 + B1 * B1 + B2 * B2;
    float x1 = 2.f * bb * n1 * n1;
    float tr = xx + yy + zz;
    float ms = xx * xx + yy * yy + zz * zz + 2.f * (xy * xy + xz * xz + yz * yz);
    float x2 = (ms - tr * tr * (1.f / 3.f)) * n2 * n2;

    __shared__ float red[4];
    float v = x0 + x1 + x2;
    #pragma unroll
    for (int o = 16; o; o >>= 1) v += __shfl_xor_sync(0xffffffffu, v, o);
    if ((k & 31) == 0) red[k >> 5] = v;
    __syncthreads();
    float mean = (red[0] + red[1] + red[2] + red[3]) * (1.f / 384.f);
    __syncthreads();
    float d0 = x0 - mean, d1 = x1 - mean, d2 = x2 - mean;
    v = d0 * d0 + d1 * d1 + d2 * d2;
    #pragma unroll
    for (int o = 16; o; o >>= 1) v += __shfl_xor_sync(0xffffffffu, v, o);
    if ((k & 31) == 0) red[k >> 5] = v;
    __syncthreads();
    float var = (red[0] + red[1] + red[2] + red[3]) * (1.f / 384.f);
    float rs = rsqrtf(var + 1e-5f);
    float o0 = d0 * rs * gam[k]       + bet[k];
    float o1 = d1 * rs * gam[128 + k] + bet[128 + k];
    float o2 = d2 * rs * gam[256 + k] + bet[256 + k];
    bf16 hh, ll;
    split1(o0, hh, ll); g_XNH[n * 384 + k]       = hh; g_XNL[n * 384 + k]       = ll;
    split1(o1, hh, ll); g_XNH[n * 384 + 128 + k] = hh; g_XNL[n * 384 + 128 + k] = ll;
    split1(o2, hh, ll); g_XNH[n * 384 + 256 + k] = hh; g_XNL[n * 384 + 256 + k] = ll;
}

// ---------------- launch ----------------
extern "C" void kernel_launch(void* const* d_in, const int* in_sizes, int n_in,
                              void* d_out, int out_size) {
    const int*   z      = (const int*)d_in[0];
    const float* pos    = (const float*)d_in[1];
    const int*   ei     = (const int*)d_in[3];
    const float* emb_w  = (const float*)d_in[4];
    const float* emb2_w = (const float*)d_in[5];
    const float* emb2_b = (const float*)d_in[6];
    const float* dp1w   = (const float*)d_in[7];
    const float* dp1b   = (const float*)d_in[8];
    const float* dp2w   = (const float*)d_in[9];
    const float* dp2b   = (const float*)d_in[10];
    const float* dp3w   = (const float*)d_in[11];
    const float* dp3b   = (const float*)d_in[12];
    const float* lt0w   = (const float*)d_in[13];
    const float* lt1w   = (const float*)d_in[14];
    const float* lt2w   = (const float*)d_in[15];
    const float* ls0w   = (const float*)d_in[16];
    const float* ls0b   = (const float*)d_in[17];
    const float* ls1w   = (const float*)d_in[18];
    const float* ls1b   = (const float*)d_in[19];
    const float* ing    = (const float*)d_in[20];
    const float* inb    = (const float*)d_in[21];
    const float* linw   = (const float*)d_in[22];
    const float* linb   = (const float*)d_in[23];
    const float* ong    = (const float*)d_in[24];
    const float* onb    = (const float*)d_in[25];
    const float* ol1w   = (const float*)d_in[26];
    const float* ol1b   = (const float*)d_in[27];
    const float* ol2w   = (const float*)d_in[28];
    const float* ol2b   = (const float*)d_in[29];
    float* y = (float*)d_out;

    cudaFuncSetAttribute(tg_mixls0, cudaFuncAttributeMaxDynamicSharedMemorySize, TG_SMEM);
    cudaFuncSetAttribute(tg_ls1, cudaFuncAttributeMaxDynamicSharedMemorySize, TG_SMEM);
    cudaFuncSetAttribute(tg_tail, cudaFuncAttributeMaxDynamicSharedMemorySize, TG_SMEM);
    cudaFuncSetAttribute(k_edgedp, cudaFuncAttributeMaxDynamicSharedMemorySize, EDP_SMEM);

    k_count<<<368, 256>>>(ei, pos, emb_w, emb2_w, emb2_b,
                          dp1w, dp1b, dp2w, dp2b, dp3w, dp3b);
    k_scan<<<1, 1024>>>();
    k_scatter<<<NE / 256, 256>>>(ei, pos, z);
    k_edgedp<<<EDP_BLOCKS, 256, EDP_SMEM>>>();
    k_gather<<<NN, 128>>>(z, ing, inb);
    k_wprep<<<928, 256>>>(ls0w, ls1w, linw, lt0w, lt1w, lt2w, ol1w);
    tg_mixls0<<<1536, 256, TG_SMEM>>>(ls0b);
    tg_ls1<<<dim3(NN / 128, 3), 256, TG_SMEM>>>(ls1b);
    k_combine_ln<<<NN, 128>>>(ong, onb);
    tg_tail<<<NN / 128, 256, TG_SMEM>>>(linb, ol1b, ol2w, ol2b, y);
}

// round 17
// speedup vs baseline: 1.0508x; 1.0289x over previous
#include <cuda_runtime.h>
#include <cuda_bf16.h>
#include <math.h>
#include <stdint.h>

#define NN 16384
#define NE 65536
typedef __nv_bfloat16 bf16;

// ---------------- fp32 scratch ----------------
static __device__ __align__(256) float g_U[128 * 128];
static __device__ __align__(256) float g_V[128 * 128];
static __device__ __align__(256) float g_NR[NN * 384];
static __device__ __align__(256) float g_Ip[NN * 128];
static __device__ __align__(256) float g_Bsq[NN * 128];
static __device__ __align__(256) float g_ms[NN * 128];
static __device__ __align__(256) float g_tr[NN * 128];
static __device__ __align__(256) float g_Wt[32 * 384];
static __device__ __align__(256) float g_db[384];
static __device__ __align__(256) float g_edp[(size_t)NE * 384];
static __device__ int g_Etot;

// ---------------- bf16 hi/lo activations ----------------
static __device__ __align__(256) bf16 g_accH[10 * NN * 128], g_accL[10 * NN * 128];
static __device__ __align__(256) bf16 g_TH[NN * 128],  g_TL[NN * 128];
static __device__ __align__(256) bf16 g_H1H[NN * 256], g_H1L[NN * 256];
static __device__ __align__(256) bf16 g_XNH[NN * 384], g_XNL[NN * 384];

// ---------------- bf16 hi/lo weights ----------------
static __device__ __align__(256) bf16 w_ls0H[256 * 128], w_ls0L[256 * 128];
static __device__ __align__(256) bf16 w_ls1H[384 * 256], w_ls1L[384 * 256];
static __device__ __align__(256) bf16 w_linH[128 * 384], w_linL[128 * 384];
static __device__ __align__(256) bf16 w_ltH[3 * 128 * 128], w_ltL[3 * 128 * 128];
static __device__ __align__(256) bf16 w_ol1H[64 * 128], w_ol1L[64 * 128];

// ---------------- CSR edge compaction ----------------
static __device__ __align__(256) int    g_cnt[NN];
static __device__ __align__(256) int    g_off[NN];
static __device__ __align__(256) int    g_fill[NN];
static __device__ __align__(256) float4 g_erec[NE];
static __device__ __align__(256) int    g_ez[NE];

__device__ __forceinline__ float silu(float x) { return x / (1.f + expf(-x)); }
__device__ __forceinline__ void split1(float v, bf16& h, bf16& l) {
    h = __float2bfloat16(v);
    l = __float2bfloat16(v - __bfloat162float(h));
}

#define RBF_START 0.011108996538242306
#define RBF_BETA  (1.0 / ((0.0625 * (1.0 - RBF_START)) * (0.0625 * (1.0 - RBF_START))))
#define RBF_ALPHA (5.0 / 4.5)
#define PI_OVER_C 0.6981317007977318

// =================== MMA plumbing ===================
__device__ __forceinline__ uint32_t smem_u32(const void* p) {
    uint32_t a;
    asm("{ .reg .u64 t; cvta.to.shared.u64 t, %1; cvt.u32.u64 %0, t; }" : "=r"(a) : "l"(p));
    return a;
}
__device__ __forceinline__ void ldm_x4(uint32_t addr, uint32_t* r) {
    asm volatile("ldmatrix.sync.aligned.m8n8.x4.shared.b16 {%0,%1,%2,%3}, [%4];"
                 : "=r"(r[0]), "=r"(r[1]), "=r"(r[2]), "=r"(r[3]) : "r"(addr));
}
__device__ __forceinline__ void mma16816(float* c, const uint32_t* a, const uint32_t* b) {
    asm volatile("mma.sync.aligned.m16n8k16.row.col.f32.bf16.bf16.f32 "
                 "{%0,%1,%2,%3}, {%4,%5,%6,%7}, {%8,%9}, {%0,%1,%2,%3};"
                 : "+f"(c[0]), "+f"(c[1]), "+f"(c[2]), "+f"(c[3])
                 : "r"(a[0]), "r"(a[1]), "r"(a[2]), "r"(a[3]), "r"(b[0]), "r"(b[1]));
}
__device__ __forceinline__ void cpa16(uint32_t s, const void* g) {
    asm volatile("cp.async.cg.shared.global [%0], [%1], 16;" :: "r"(s), "l"(g));
}
#define CP_COMMIT() asm volatile("cp.async.commit_group;")
#define CP_WAIT0()  asm volatile("cp.async.wait_group 0;" ::: "memory")

#define TPAD 136
#define SM_A (128 * TPAD * 2)
#define SM_W (64 * TPAD * 2)
#define TG_SMEM (2 * SM_A + 2 * SM_W)   // 104448 -> 2 CTAs/SM

template <int OUT, int FT>
__device__ __forceinline__ void mma_gemm_bf(
    int bx, int by,
    const bf16* __restrict__ AH, const bf16* __restrict__ AL,
    const bf16* __restrict__ WH, const bf16* __restrict__ WL,
    const float* __restrict__ bias,
    float* __restrict__ C, bf16* __restrict__ CH, bf16* __restrict__ CL,
    int K, int F, bool act) {
    extern __shared__ __align__(16) char smem[];
    const uint32_t aH_u = smem_u32(smem);
    const uint32_t aL_u = aH_u + SM_A;
    const uint32_t wH_u = aH_u + 2 * SM_A;
    const uint32_t wL_u = wH_u + SM_W;

    const int tid = threadIdx.x, lane = tid & 31, wid = tid >> 5;
    const int wm = wid & 3, wn = wid >> 2;
    const int m0 = bx << 7;
    const int f0 = by * (64 * FT);

    float c[FT][2][4][4];
    #pragma unroll
    for (int ft = 0; ft < FT; ft++)
        #pragma unroll
        for (int i = 0; i < 2; i++)
            #pragma unroll
            for (int j = 0; j < 4; j++)
                #pragma unroll
                for (int q = 0; q < 4; q++) c[ft][i][j][q] = 0.f;

    const int a_row = wm * 32 + (lane & 15);
    const int a_col = (lane >> 4) << 3;
    const int b_row = wn * 32 + (lane & 7) + ((lane >> 4) << 3);
    const int b_col = ((lane >> 3) & 1) << 3;

    for (int kc = 0; kc < K; kc += 128) {
        __syncthreads();
        #pragma unroll
        for (int i = tid; i < 2048; i += 256) {
            int r = i >> 4, c8 = (i & 15) << 3;
            uint32_t so = (uint32_t)(r * TPAD + c8) * 2;
            size_t go = (size_t)(m0 + r) * K + kc + c8;
            cpa16(aH_u + so, AH + go);
            cpa16(aL_u + so, AL + go);
        }
        #pragma unroll
        for (int i = tid; i < 1024; i += 256) {
            int r = i >> 4, c8 = (i & 15) << 3;
            uint32_t so = (uint32_t)(r * TPAD + c8) * 2;
            size_t go = (size_t)(f0 + r) * K + kc + c8;
            cpa16(wH_u + so, WH + go);
            cpa16(wL_u + so, WL + go);
        }
        CP_COMMIT();
        CP_WAIT0();
        __syncthreads();

        #pragma unroll
        for (int ft = 0; ft < FT; ft++) {
            if (ft > 0) {
                __syncthreads();
                #pragma unroll
                for (int i = tid; i < 1024; i += 256) {
                    int r = i >> 4, c8 = (i & 15) << 3;
                    uint32_t so = (uint32_t)(r * TPAD + c8) * 2;
                    size_t go = (size_t)(f0 + ft * 64 + r) * K + kc + c8;
                    cpa16(wH_u + so, WH + go);
                    cpa16(wL_u + so, WL + go);
                }
                CP_COMMIT();
                CP_WAIT0();
                __syncthreads();
            }
            #pragma unroll
            for (int ks = 0; ks < 8; ks++) {
                uint32_t ah[2][4], al[2][4];
                #pragma unroll
                for (int mf = 0; mf < 2; mf++) {
                    uint32_t off = (uint32_t)((a_row + mf * 16) * TPAD + a_col + ks * 16) * 2;
                    ldm_x4(aH_u + off, ah[mf]);
                    ldm_x4(aL_u + off, al[mf]);
                }
                #pragma unroll
                for (int nfp = 0; nfp < 2; nfp++) {
                    uint32_t boff = (uint32_t)((b_row + nfp * 16) * TPAD + b_col + ks * 16) * 2;
                    uint32_t bh[4], bl[4];
                    ldm_x4(wH_u + boff, bh);
                    ldm_x4(wL_u + boff, bl);
                    #pragma unroll
                    for (int mf = 0; mf < 2; mf++) {
                        mma16816(c[ft][mf][2 * nfp], ah[mf], bh);
                        mma16816(c[ft][mf][2 * nfp], ah[mf], bl);
                        mma16816(c[ft][mf][2 * nfp], al[mf], bh);
                        mma16816(c[ft][mf][2 * nfp + 1], ah[mf], bh + 2);
                        mma16816(c[ft][mf][2 * nfp + 1], ah[mf], bl + 2);
                        mma16816(c[ft][mf][2 * nfp + 1], al[mf], bh + 2);
                    }
                }
            }
        }
    }

    #pragma unroll
    for (int ft = 0; ft < FT; ft++) {
        #pragma unroll
        for (int mf = 0; mf < 2; mf++) {
            #pragma unroll
            for (int nf = 0; nf < 4; nf++) {
                int grow = m0 + wm * 32 + mf * 16 + (lane >> 2);
                int gcol = f0 + ft * 64 + wn * 32 + nf * 8 + ((lane & 3) << 1);
                float b0 = bias ? bias[gcol] : 0.f;
                float b1 = bias ? bias[gcol + 1] : 0.f;
                float v0 = c[ft][mf][nf][0] + b0, v1 = c[ft][mf][nf][1] + b1;
                float v2 = c[ft][mf][nf][2] + b0, v3 = c[ft][mf][nf][3] + b1;
                if (act) { v0 = silu(v0); v1 = silu(v1); v2 = silu(v2); v3 = silu(v3); }
                if (OUT == 0) {
                    *(float2*)&C[(size_t)grow * F + gcol] = make_float2(v0, v1);
                    *(float2*)&C[(size_t)(grow + 8) * F + gcol] = make_float2(v2, v3);
                } else {
                    bf16 h0, l0, h1, l1;
                    split1(v0, h0, l0); split1(v1, h1, l1);
                    *(__nv_bfloat162*)&CH[(size_t)grow * F + gcol] = __halves2bfloat162(h0, h1);
                    *(__nv_bfloat162*)&CL[(size_t)grow * F + gcol] = __halves2bfloat162(l0, l1);
                    split1(v2, h0, l0); split1(v3, h1, l1);
                    *(__nv_bfloat162*)&CH[(size_t)(grow + 8) * F + gcol] = __halves2bfloat162(h0, h1);
                    *(__nv_bfloat162*)&CL[(size_t)(grow + 8) * F + gcol] = __halves2bfloat162(l0, l1);
                }
            }
        }
    }
}

// ---- grouped mix GEMM: loop planes with resident weight tile, square-accumulate ----
// MODE 0: write c (Ip). MODE 1: write sum of c^2 (Bsq). MODE 2: write ms (+tr).
template <int MODE>
__device__ __forceinline__ void mix_group(
    int bx, int by, int plane_base, int npass,
    const bf16* __restrict__ WH, const bf16* __restrict__ WL,
    float* __restrict__ out1, float* __restrict__ out2) {
    extern __shared__ __align__(16) char smem[];
    const uint32_t aH_u = smem_u32(smem);
    const uint32_t aL_u = aH_u + SM_A;
    const uint32_t wH_u = aH_u + 2 * SM_A;
    const uint32_t wL_u = wH_u + SM_W;

    const int tid = threadIdx.x, lane = tid & 31, wid = tid >> 5;
    const int wm = wid & 3, wn = wid >> 2;
    const int m0 = bx << 7;
    const int f0 = by << 6;

    const int a_row = wm * 32 + (lane & 15);
    const int a_col = (lane >> 4) << 3;
    const int b_row = wn * 32 + (lane & 7) + ((lane >> 4) << 3);
    const int b_col = ((lane >> 3) & 1) << 3;

    // W tile loaded once (64 rows of [128,128] weight)
    #pragma unroll
    for (int i = tid; i < 1024; i += 256) {
        int r = i >> 4, c8 = (i & 15) << 3;
        uint32_t so = (uint32_t)(r * TPAD + c8) * 2;
        size_t go = (size_t)(f0 + r) * 128 + c8;
        cpa16(wH_u + so, WH + go);
        cpa16(wL_u + so, WL + go);
    }
    CP_COMMIT();

    float sq[2][4][4], trr[2][4][4], c[2][4][4];
    if (MODE >= 1) {
        #pragma unroll
        for (int i = 0; i < 2; i++)
            #pragma unroll
            for (int j = 0; j < 4; j++)
                #pragma unroll
                for (int q = 0; q < 4; q++) sq[i][j][q] = 0.f;
    }
    if (MODE == 2) {
        #pragma unroll
        for (int i = 0; i < 2; i++)
            #pragma unroll
            for (int j = 0; j < 4; j++)
                #pragma unroll
                for (int q = 0; q < 4; q++) trr[i][j][q] = 0.f;
    }

    for (int p = 0; p < npass; p++) {
        __syncthreads();   // prior pass's smem reads done
        const bf16* AH = g_accH + (size_t)(plane_base + p) * (NN * 128) + (size_t)m0 * 128;
        const bf16* AL = g_accL + (size_t)(plane_base + p) * (NN * 128) + (size_t)m0 * 128;
        #pragma unroll
        for (int i = tid; i < 2048; i += 256) {
            int r = i >> 4, c8 = (i & 15) << 3;
            uint32_t so = (uint32_t)(r * TPAD + c8) * 2;
            size_t go = (size_t)r * 128 + c8;
            cpa16(aH_u + so, AH + go);
            cpa16(aL_u + so, AL + go);
        }
        CP_COMMIT();
        CP_WAIT0();
        __syncthreads();

        #pragma unroll
        for (int i = 0; i < 2; i++)
            #pragma unroll
            for (int j = 0; j < 4; j++)
                #pragma unroll
                for (int q = 0; q < 4; q++) c[i][j][q] = 0.f;

        #pragma unroll
        for (int ks = 0; ks < 8; ks++) {
            uint32_t ah[2][4], al[2][4];
            #pragma unroll
            for (int mf = 0; mf < 2; mf++) {
                uint32_t off = (uint32_t)((a_row + mf * 16) * TPAD + a_col + ks * 16) * 2;
                ldm_x4(aH_u + off, ah[mf]);
                ldm_x4(aL_u + off, al[mf]);
            }
            #pragma unroll
            for (int nfp = 0; nfp < 2; nfp++) {
                uint32_t boff = (uint32_t)((b_row + nfp * 16) * TPAD + b_col + ks * 16) * 2;
                uint32_t bh[4], bl[4];
                ldm_x4(wH_u + boff, bh);
                ldm_x4(wL_u + boff, bl);
                #pragma unroll
                for (int mf = 0; mf < 2; mf++) {
                    mma16816(c[mf][2 * nfp], ah[mf], bh);
                    mma16816(c[mf][2 * nfp], ah[mf], bl);
                    mma16816(c[mf][2 * nfp], al[mf], bh);
                    mma16816(c[mf][2 * nfp + 1], ah[mf], bh + 2);
                    mma16816(c[mf][2 * nfp + 1], ah[mf], bl + 2);
                    mma16816(c[mf][2 * nfp + 1], al[mf], bh + 2);
                }
            }
        }

        if (MODE >= 1) {
            float w = (MODE == 2 && p >= 3) ? 2.f : 1.f;
            #pragma unroll
            for (int i = 0; i < 2; i++)
                #pragma unroll
                for (int j = 0; j < 4; j++)
                    #pragma unroll
                    for (int q = 0; q < 4; q++)
                        sq[i][j][q] = fmaf(w * c[i][j][q], c[i][j][q], sq[i][j][q]);
            if (MODE == 2 && p < 3) {
                #pragma unroll
                for (int i = 0; i < 2; i++)
                    #pragma unroll
                    for (int j = 0; j < 4; j++)
                        #pragma unroll
                        for (int q = 0; q < 4; q++) trr[i][j][q] += c[i][j][q];
            }
        }
    }

    #pragma unroll
    for (int mf = 0; mf < 2; mf++) {
        #pragma unroll
        for (int nf = 0; nf < 4; nf++) {
            int grow = m0 + wm * 32 + mf * 16 + (lane >> 2);
            int gcol = f0 + wn * 32 + nf * 8 + ((lane & 3) << 1);
            if (MODE == 0) {
                *(float2*)&out1[(size_t)grow * 128 + gcol] = make_float2(c[mf][nf][0], c[mf][nf][1]);
                *(float2*)&out1[(size_t)(grow + 8) * 128 + gcol] = make_float2(c[mf][nf][2], c[mf][nf][3]);
            } else {
                *(float2*)&out1[(size_t)grow * 128 + gcol] = make_float2(sq[mf][nf][0], sq[mf][nf][1]);
                *(float2*)&out1[(size_t)(grow + 8) * 128 + gcol] = make_float2(sq[mf][nf][2], sq[mf][nf][3]);
                if (MODE == 2) {
                    *(float2*)&out2[(size_t)grow * 128 + gcol] = make_float2(trr[mf][nf][0], trr[mf][nf][1]);
                    *(float2*)&out2[(size_t)(grow + 8) * 128 + gcol] = make_float2(trr[mf][nf][2], trr[mf][nf][3]);
                }
            }
        }
    }
}

// mix groups (I, B, S) + ls0, one launch: 1024 blocks
__global__ __launch_bounds__(256, 2)
void tc_mix2(const float* __restrict__ ls0b) {
    int bid = blockIdx.x;
    if (bid < 256) {
        mix_group<0>(bid & 127, bid >> 7, 0, 1, w_ltH, w_ltL, g_Ip, nullptr);
    } else if (bid < 512) {
        int b = bid - 256;
        mix_group<1>(b & 127, b >> 7, 1, 3, w_ltH + 16384, w_ltL + 16384, g_Bsq, nullptr);
    } else if (bid < 768) {
        int b = bid - 512;
        mix_group<2>(b & 127, b >> 7, 4, 6, w_ltH + 32768, w_ltL + 32768, g_ms, g_tr);
    } else {
        int b = bid - 768;
        mma_gemm_bf<1, 2>(b & 127, b >> 7, g_TH, g_TL, w_ls0H, w_ls0L, ls0b,
                          nullptr, g_H1H, g_H1L, 128, 256, true);
    }
}
__global__ __launch_bounds__(256, 2)
void tg_ls1(const float* __restrict__ b) {
    mma_gemm_bf<0, 2>(blockIdx.x, blockIdx.y, g_H1H, g_H1L, w_ls1H, w_ls1L, b,
                      g_NR, nullptr, nullptr, 256, 384, true);
}

// =================== fused tail: lin GEMM -> ol1 GEMM -> final dot ===================
__global__ __launch_bounds__(256, 2)
void tg_tail(const float* __restrict__ linb, const float* __restrict__ ol1b,
             const float* __restrict__ ol2w, const float* __restrict__ ol2b,
             float* __restrict__ y) {
    extern __shared__ __align__(16) char smem[];
    const uint32_t aH_u = smem_u32(smem);
    const uint32_t aL_u = aH_u + SM_A;
    const uint32_t wH_u = aH_u + 2 * SM_A;
    const uint32_t wL_u = wH_u + SM_W;
    __shared__ float ypart[128];

    const int tid = threadIdx.x, lane = tid & 31, wid = tid >> 5;
    const int wm = wid & 3, wn = wid >> 2;
    const int m0 = blockIdx.x << 7;

    const int a_row = wm * 32 + (lane & 15);
    const int a_col = (lane >> 4) << 3;
    const int b_row = wn * 32 + (lane & 7) + ((lane >> 4) << 3);
    const int b_col = ((lane >> 3) & 1) << 3;

    float c[2][2][4][4];
    #pragma unroll
    for (int ft = 0; ft < 2; ft++)
        #pragma unroll
        for (int i = 0; i < 2; i++)
            #pragma unroll
            for (int j = 0; j < 4; j++)
                #pragma unroll
                for (int q = 0; q < 4; q++) c[ft][i][j][q] = 0.f;

    for (int kc = 0; kc < 384; kc += 128) {
        __syncthreads();
        #pragma unroll
        for (int i = tid; i < 2048; i += 256) {
            int r = i >> 4, c8 = (i & 15) << 3;
            uint32_t so = (uint32_t)(r * TPAD + c8) * 2;
            size_t go = (size_t)(m0 + r) * 384 + kc + c8;
            cpa16(aH_u + so, g_XNH + go);
            cpa16(aL_u + so, g_XNL + go);
        }
        #pragma unroll
        for (int i = tid; i < 1024; i += 256) {
            int r = i >> 4, c8 = (i & 15) << 3;
            uint32_t so = (uint32_t)(r * TPAD + c8) * 2;
            size_t go = (size_t)r * 384 + kc + c8;
            cpa16(wH_u + so, w_linH + go);
            cpa16(wL_u + so, w_linL + go);
        }
        CP_COMMIT();
        CP_WAIT0();
        __syncthreads();

        #pragma unroll
        for (int ft = 0; ft < 2; ft++) {
            if (ft > 0) {
                __syncthreads();
                #pragma unroll
                for (int i = tid; i < 1024; i += 256) {
                    int r = i >> 4, c8 = (i & 15) << 3;
                    uint32_t so = (uint32_t)(r * TPAD + c8) * 2;
                    size_t go = (size_t)(64 + r) * 384 + kc + c8;
                    cpa16(wH_u + so, w_linH + go);
                    cpa16(wL_u + so, w_linL + go);
                }
                CP_COMMIT();
                CP_WAIT0();
                __syncthreads();
            }
            #pragma unroll
            for (int ks = 0; ks < 8; ks++) {
                uint32_t ah[2][4], al[2][4];
                #pragma unroll
                for (int mf = 0; mf < 2; mf++) {
                    uint32_t off = (uint32_t)((a_row + mf * 16) * TPAD + a_col + ks * 16) * 2;
                    ldm_x4(aH_u + off, ah[mf]);
                    ldm_x4(aL_u + off, al[mf]);
                }
                #pragma unroll
                for (int nfp = 0; nfp < 2; nfp++) {
                    uint32_t boff = (uint32_t)((b_row + nfp * 16) * TPAD + b_col + ks * 16) * 2;
                    uint32_t bh[4], bl[4];
                    ldm_x4(wH_u + boff, bh);
                    ldm_x4(wL_u + boff, bl);
                    #pragma unroll
                    for (int mf = 0; mf < 2; mf++) {
                        mma16816(c[ft][mf][2 * nfp], ah[mf], bh);
                        mma16816(c[ft][mf][2 * nfp], ah[mf], bl);
                        mma16816(c[ft][mf][2 * nfp], al[mf], bh);
                        mma16816(c[ft][mf][2 * nfp + 1], ah[mf], bh + 2);
                        mma16816(c[ft][mf][2 * nfp + 1], ah[mf], bl + 2);
                        mma16816(c[ft][mf][2 * nfp + 1], al[mf], bh + 2);
                    }
                }
            }
        }
    }

    __syncthreads();
    #pragma unroll
    for (int ft = 0; ft < 2; ft++) {
        #pragma unroll
        for (int mf = 0; mf < 2; mf++) {
            #pragma unroll
            for (int nf = 0; nf < 4; nf++) {
                int lrow = wm * 32 + mf * 16 + (lane >> 2);
                int lcol = ft * 64 + wn * 32 + nf * 8 + ((lane & 3) << 1);
                float b0 = linb[lcol], b1 = linb[lcol + 1];
                float v0 = silu(c[ft][mf][nf][0] + b0);
                float v1 = silu(c[ft][mf][nf][1] + b1);
                float v2 = silu(c[ft][mf][nf][2] + b0);
                float v3 = silu(c[ft][mf][nf][3] + b1);
                bf16 h0, l0, h1, l1;
                split1(v0, h0, l0); split1(v1, h1, l1);
                *(__nv_bfloat162*)(smem + (size_t)(lrow * TPAD + lcol) * 2) =
                    __halves2bfloat162(h0, h1);
                *(__nv_bfloat162*)(smem + SM_A + (size_t)(lrow * TPAD + lcol) * 2) =
                    __halves2bfloat162(l0, l1);
                split1(v2, h0, l0); split1(v3, h1, l1);
                *(__nv_bfloat162*)(smem + (size_t)((lrow + 8) * TPAD + lcol) * 2) =
                    __halves2bfloat162(h0, h1);
                *(__nv_bfloat162*)(smem + SM_A + (size_t)((lrow + 8) * TPAD + lcol) * 2) =
                    __halves2bfloat162(l0, l1);
            }
        }
    }
    #pragma unroll
    for (int i = tid; i < 1024; i += 256) {
        int r = i >> 4, c8 = (i & 15) << 3;
        if (r < 64) {
            uint32_t so = (uint32_t)(r * TPAD + c8) * 2;
            cpa16(wH_u + so, w_ol1H + r * 128 + c8);
            cpa16(wL_u + so, w_ol1L + r * 128 + c8);
        }
    }
    CP_COMMIT();
    CP_WAIT0();
    if (tid < 128) ypart[tid] = 0.f;
    __syncthreads();

    float c2[2][4][4];
    #pragma unroll
    for (int i = 0; i < 2; i++)
        #pragma unroll
        for (int j = 0; j < 4; j++)
            #pragma unroll
            for (int q = 0; q < 4; q++) c2[i][j][q] = 0.f;

    #pragma unroll
    for (int ks = 0; ks < 8; ks++) {
        uint32_t ah[2][4], al[2][4];
        #pragma unroll
        for (int mf = 0; mf < 2; mf++) {
            uint32_t off = (uint32_t)((a_row + mf * 16) * TPAD + a_col + ks * 16) * 2;
            ldm_x4(aH_u + off, ah[mf]);
            ldm_x4(aL_u + off, al[mf]);
        }
        #pragma unroll
        for (int nfp = 0; nfp < 2; nfp++) {
            uint32_t boff = (uint32_t)((b_row + nfp * 16) * TPAD + b_col + ks * 16) * 2;
            uint32_t bh[4], bl[4];
            ldm_x4(wH_u + boff, bh);
            ldm_x4(wL_u + boff, bl);
            #pragma unroll
            for (int mf = 0; mf < 2; mf++) {
                mma16816(c2[mf][2 * nfp], ah[mf], bh);
                mma16816(c2[mf][2 * nfp], ah[mf], bl);
                mma16816(c2[mf][2 * nfp], al[mf], bh);
                mma16816(c2[mf][2 * nfp + 1], ah[mf], bh + 2);
                mma16816(c2[mf][2 * nfp + 1], ah[mf], bl + 2);
                mma16816(c2[mf][2 * nfp + 1], al[mf], bh + 2);
            }
        }
    }

    #pragma unroll
    for (int mf = 0; mf < 2; mf++) {
        float pr0 = 0.f, pr8 = 0.f;
        #pragma unroll
        for (int nf = 0; nf < 4; nf++) {
            int gcol = wn * 32 + nf * 8 + ((lane & 3) << 1);
            float b0 = ol1b[gcol], b1 = ol1b[gcol + 1];
            float w0 = ol2w[gcol], w1 = ol2w[gcol + 1];
            pr0 += silu(c2[mf][nf][0] + b0) * w0 + silu(c2[mf][nf][1] + b1) * w1;
            pr8 += silu(c2[mf][nf][2] + b0) * w0 + silu(c2[mf][nf][3] + b1) * w1;
        }
        int lrow = wm * 32 + mf * 16 + (lane >> 2);
        atomicAdd(&ypart[lrow], pr0);
        atomicAdd(&ypart[lrow + 8], pr8);
    }
    __syncthreads();
    if (tid < 128) y[m0 + tid] = ypart[tid] + ol2b[0];
}

// ---------------- weight pre-split ----------------
__global__ void k_wprep(const float* __restrict__ ls0w, const float* __restrict__ ls1w,
                        const float* __restrict__ linw, const float* __restrict__ lt0w,
                        const float* __restrict__ lt1w, const float* __restrict__ lt2w,
                        const float* __restrict__ ol1w) {
    int j = blockIdx.x * 256 + threadIdx.x;
    const float* src; bf16 *dh, *dl;
    if (j < 32768) { src = ls0w; dh = w_ls0H; dl = w_ls0L; }
    else if ((j -= 32768) < 98304) { src = ls1w; dh = w_ls1H; dl = w_ls1L; }
    else if ((j -= 98304) < 49152) { src = linw; dh = w_linH; dl = w_linL; }
    else if ((j -= 49152) < 16384) { src = lt0w; dh = w_ltH; dl = w_ltL; }
    else if ((j -= 16384) < 16384) { src = lt1w; dh = w_ltH + 16384; dl = w_ltL + 16384; }
    else if ((j -= 16384) < 16384) { src = lt2w; dh = w_ltH + 32768; dl = w_ltL + 32768; }
    else if ((j -= 16384) < 8192)  { src = ol1w; dh = w_ol1H; dl = w_ol1L; }
    else return;
    bf16 h, l;
    split1(src[j], h, l);
    dh[j] = h; dl[j] = l;
}

// =================== launch #1: edge count + U/V tables + dp transpose ===================
__global__ void k_count(const int* __restrict__ ei, const float* __restrict__ pos,
                        const float* __restrict__ emb_w, const float* __restrict__ emb2_w,
                        const float* __restrict__ emb2_b,
                        const float* __restrict__ dp1w, const float* __restrict__ dp1b,
                        const float* __restrict__ dp2w, const float* __restrict__ dp2b,
                        const float* __restrict__ dp3w, const float* __restrict__ dp3b) {
    int b = blockIdx.x;
    if (b < 256) {
        int e = b * 256 + threadIdx.x;
        int src = ei[e], dst = ei[NE + e];
        float vx = pos[src * 3 + 0] - pos[dst * 3 + 0];
        float vy = pos[src * 3 + 1] - pos[dst * 3 + 1];
        float vz = pos[src * 3 + 2] - pos[dst * 3 + 2];
        float d = sqrtf(vx * vx + vy * vy + vz * vz);
        if (src == dst || d < 4.5f) atomicAdd(&g_cnt[src], 1);
    } else if (b < 320) {
        int zt = ((b - 256) << 1) | (threadIdx.x >> 7);
        int h = threadIdx.x & 127;
        float u = emb2_b[h];
        float v = 0.f;
        #pragma unroll 4
        for (int k = 0; k < 128; k++) {
            float e = emb_w[zt * 128 + k];
            u = fmaf(e, emb2_w[h * 256 + k], u);
            v = fmaf(e, emb2_w[h * 256 + 128 + k], v);
        }
        g_U[zt * 128 + h] = u;
        g_V[zt * 128 + h] = v;
    } else {
        int j = (b - 320) * 256 + threadIdx.x;
        int r = j / 384, col = j - r * 384;
        float v = col < 128 ? dp1w[col * 32 + r]
                : col < 256 ? dp2w[(col - 128) * 32 + r]
                            : dp3w[(col - 256) * 32 + r];
        g_Wt[j] = v;
        if (j < 384)
            g_db[j] = j < 128 ? dp1b[j] : j < 256 ? dp2b[j - 128] : dp3b[j - 256];
    }
}

// launch #2: exclusive scan + total edge count
__global__ void k_scan() {
    __shared__ int ws[32];
    int t = threadIdx.x;
    int lane = t & 31, w = t >> 5;
    int base = t * 16;
    int4 v0 = *(int4*)&g_cnt[base];
    int4 v1 = *(int4*)&g_cnt[base + 4];
    int4 v2 = *(int4*)&g_cnt[base + 8];
    int4 v3 = *(int4*)&g_cnt[base + 12];
    int cv[16] = {v0.x, v0.y, v0.z, v0.w, v1.x, v1.y, v1.z, v1.w,
                  v2.x, v2.y, v2.z, v2.w, v3.x, v3.y, v3.z, v3.w};
    int local[16];
    int s = 0;
    #pragma unroll
    for (int i = 0; i < 16; i++) { local[i] = s; s += cv[i]; }
    int inc = s;
    #pragma unroll
    for (int off = 1; off < 32; off <<= 1) {
        int x = __shfl_up_sync(0xffffffffu, inc, off);
        if (lane >= off) inc += x;
    }
    if (lane == 31) ws[w] = inc;
    __syncthreads();
    if (w == 0) {
        int wi = ws[lane];
        #pragma unroll
        for (int off = 1; off < 32; off <<= 1) {
            int x = __shfl_up_sync(0xffffffffu, wi, off);
            if (lane >= off) wi += x;
        }
        ws[lane] = wi;
    }
    __syncthreads();
    int warp_pre = (w == 0) ? 0 : ws[w - 1];
    int pre = warp_pre + inc - s;
    int4 o0 = make_int4(pre + local[0], pre + local[1], pre + local[2], pre + local[3]);
    int4 o1 = make_int4(pre + local[4], pre + local[5], pre + local[6], pre + local[7]);
    int4 o2 = make_int4(pre + local[8], pre + local[9], pre + local[10], pre + local[11]);
    int4 o3 = make_int4(pre + local[12], pre + local[13], pre + local[14], pre + local[15]);
    *(int4*)&g_off[base] = o0;
    *(int4*)&g_off[base + 4] = o1;
    *(int4*)&g_off[base + 8] = o2;
    *(int4*)&g_off[base + 12] = o3;
    if (t == 1023) g_Etot = pre + local[15] + cv[15];
}

// launch #3
__global__ void k_scatter(const int* __restrict__ ei, const float* __restrict__ pos,
                          const int* __restrict__ z) {
    int e = blockIdx.x * 256 + threadIdx.x;
    if (e >= NE) return;
    int src = ei[e], dst = ei[NE + e];
    float vx = pos[src * 3 + 0] - pos[dst * 3 + 0];
    float vy = pos[src * 3 + 1] - pos[dst * 3 + 1];
    float vz = pos[src * 3 + 2] - pos[dst * 3 + 2];
    float d = sqrtf(vx * vx + vy * vy + vz * vz);
    bool selfe = (src == dst);
    if (!selfe && !(d < 4.5f)) return;
    int slot = g_off[src] + atomicAdd(&g_fill[src], 1);
    g_erec[slot] = make_float4(vx, vy, vz, d);
    g_ez[slot] = z[dst] | (selfe ? (int)0x80000000 : 0);
}

// launch #4: per-edge dp projections (R13 config: 4 edges/warp iteration)
#define EDP_SMEM ((32 * 384 + 384) * 4)
#define EDP_BLOCKS 296
__global__ __launch_bounds__(256)
void k_edgedp() {
    extern __shared__ float sdp[];
    float* sW = sdp;
    float* sb = sdp + 32 * 384;
    int tid = threadIdx.x;

    #pragma unroll 8
    for (int i = tid; i < 32 * 384; i += 256) sW[i] = g_Wt[i];
    if (tid < 128) {
        sb[tid] = g_db[tid];
        sb[128 + tid] = g_db[128 + tid];
        sb[256 + tid] = g_db[256 + tid];
    }
    __syncthreads();

    int E = g_Etot;
    int lane = tid & 31, w = tid >> 5;
    float mean = (float)RBF_START + (float)lane * (float)((1.0 - RBF_START) / 31.0);
    float bias0[12];
    #pragma unroll
    for (int c = 0; c < 12; c++) bias0[c] = sb[lane + 32 * c];

    int gw = blockIdx.x * 8 + w;
    int nw = EDP_BLOCKS * 8;
    for (int e0 = gw * 4; e0 < E; e0 += nw * 4) {
        float attr[4];
        #pragma unroll
        for (int i = 0; i < 4; i++) {
            int e = e0 + i;
            if (e < E) {
                float d = g_erec[e].w;
                float cut = 0.5f * (cosf(d * (float)PI_OVER_C) + 1.0f);
                float gex = expf(-(float)RBF_ALPHA * d);
                float diff = gex - mean;
                attr[i] = cut * expf(-(float)RBF_BETA * diff * diff);
            } else attr[i] = 0.f;
        }

        float acc[4][12];
        #pragma unroll
        for (int i = 0; i < 4; i++)
            #pragma unroll
            for (int c = 0; c < 12; c++) acc[i][c] = bias0[c];

        #pragma unroll
        for (int r = 0; r < 32; r++) {
            float a0 = __shfl_sync(0xffffffffu, attr[0], r);
            float a1 = __shfl_sync(0xffffffffu, attr[1], r);
            float a2 = __shfl_sync(0xffffffffu, attr[2], r);
            float a3 = __shfl_sync(0xffffffffu, attr[3], r);
            const float* wr = sW + r * 384 + lane;
            #pragma unroll
            for (int c = 0; c < 12; c++) {
                float wv = wr[32 * c];
                acc[0][c] = fmaf(a0, wv, acc[0][c]);
                acc[1][c] = fmaf(a1, wv, acc[1][c]);
                acc[2][c] = fmaf(a2, wv, acc[2][c]);
                acc[3][c] = fmaf(a3, wv, acc[3][c]);
            }
        }
        #pragma unroll
        for (int i = 0; i < 4; i++) {
            int e = e0 + i;
            if (e < E) {
                float* out = g_edp + (size_t)e * 384 + lane;
                #pragma unroll
                for (int c = 0; c < 12; c++) out[32 * c] = acc[i][c];
            }
        }
    }
}

// launch #5: gather + tensor-norm + layernorm(128)
__global__ void k_gather(const int* __restrict__ z,
                         const float* __restrict__ gam, const float* __restrict__ bet) {
    int n = blockIdx.x, h = threadIdx.x;
    __shared__ float red[4];

    int cnt = g_cnt[n];
    int off = g_off[n];
    int zn = z[n];
    float Un = g_U[(zn << 7) + h];

    float a = 0.f, bx = 0.f, by = 0.f, bz = 0.f;
    float xx = 0.f, yy = 0.f, zz = 0.f, xy = 0.f, xz = 0.f, yz = 0.f;

    for (int j = 0; j < cnt; j++) {
        int e = off + j;
        float4 rec = g_erec[e];
        int ezd = g_ez[e];
        bool selfe = (ezd < 0);
        int zdst = ezd & 127;
        float d = rec.w;
        float cut = 0.5f * (cosf(d * (float)PI_OVER_C) + 1.0f);
        float inv = selfe ? 1.0f : (1.0f / d);
        float vx = rec.x * inv, vy = rec.y * inv, vz = rec.z * inv;

        const float* dp = g_edp + (size_t)e * 384 + h;
        float d1 = dp[0], d2 = dp[128], d3 = dp[256];
        float C = cut * (Un + g_V[(zdst << 7) + h]);

        float ai = d1 * C, cb = d2 * C, cs = d3 * C;
        a  += ai;
        bx += cb * vx; by += cb * vy; bz += cb * vz;
        xx += cs * vx * vx; yy += cs * vy * vy; zz += cs * vz * vz;
        xy += cs * vx * vy; xz += cs * vx * vz; yz += cs * vy * vz;
    }

    int i = (n << 7) + h;
    float vals[10] = {a, bx, by, bz, xx, yy, zz, xy, xz, yz};
    #pragma unroll
    for (int p = 0; p < 10; p++) {
        bf16 hh, ll;
        split1(vals[p], hh, ll);
        g_accH[(size_t)p * (NN * 128) + i] = hh;
        g_accL[(size_t)p * (NN * 128) + i] = ll;
    }

    float tr = xx + yy + zz;
    float ms = xx * xx + yy * yy + zz * zz + 2.f * (xy * xy + xz * xz + yz * yz);
    float tn = 3.f * a * a + 2.f * (bx * bx + by * by + bz * bz) + ms - tr * tr * (1.f / 3.f);

    float v = tn;
    #pragma unroll
    for (int o = 16; o; o >>= 1) v += __shfl_xor_sync(0xffffffffu, v, o);
    if ((h & 31) == 0) red[h >> 5] = v;
    __syncthreads();
    float mean = (red[0] + red[1] + red[2] + red[3]) * (1.f / 128.f);
    float dev = tn - mean;
    v = dev * dev;
    #pragma unroll
    for (int o = 16; o; o >>= 1) v += __shfl_xor_sync(0xffffffffu, v, o);
    __syncthreads();
    if ((h & 31) == 0) red[h >> 5] = v;
    __syncthreads();
    float var = (red[0] + red[1] + red[2] + red[3]) * (1.f / 128.f);
    float T = dev * rsqrtf(var + 1e-5f) * gam[h] + bet[h];
    bf16 th, tl;
    split1(T, th, tl);
    g_TH[i] = th; g_TL[i] = tl;

    if (h == 0) { g_cnt[n] = 0; g_fill[n] = 0; }
}

// ---------------- combine + layernorm(384), reads reduced mix outputs ----------------
__global__ void k_combine_ln(const float* __restrict__ gam, const float* __restrict__ bet) {
    int n = blockIdx.x, k = threadIdx.x;
    int idx = (n << 7) + k;
    float Ip = g_Ip[idx];
    float bb = g_Bsq[idx];
    float tr = g_tr[idx];
    float ms = g_ms[idx];
    const float* nr = &g_NR[n * 384 + 3 * k];
    float n0 = nr[0], n1 = nr[1], n2 = nr[2];
    float t  = Ip * n0;
    float x0 = 3.f * t * t;
    float x1 = 2.f * bb * n1 * n1;
    float x2 = (ms - tr * tr * (1.f / 3.f)) * n2 * n2;

    __shared__ float red[4];
    float v = x0 + x1 + x2;
    #pragma unroll
    for (int o = 16; o; o >>= 1) v += __shfl_xor_sync(0xffffffffu, v, o);
    if ((k & 31) == 0) red[k >> 5] = v;
    __syncthreads();
    float mean = (red[0] + red[1] + red[2] + red[3]) * (1.f / 384.f);
    __syncthreads();
    float d0 = x0 - mean, d1 = x1 - mean, d2 = x2 - mean;
    v = d0 * d0 + d1 * d1 + d2 * d2;
    #pragma unroll
    for (int o = 16; o; o >>= 1) v += __shfl_xor_sync(0xffffffffu, v, o);
    if ((k & 31) == 0) red[k >> 5] = v;
    __syncthreads();
    float var = (red[0] + red[1] + red[2] + red[3]) * (1.f / 384.f);
    float rs = rsqrtf(var + 1e-5f);
    float o0 = d0 * rs * gam[k]       + bet[k];
    float o1 = d1 * rs * gam[128 + k] + bet[128 + k];
    float o2 = d2 * rs * gam[256 + k] + bet[256 + k];
    bf16 hh, ll;
    split1(o0, hh, ll); g_XNH[n * 384 + k]       = hh; g_XNL[n * 384 + k]       = ll;
    split1(o1, hh, ll); g_XNH[n * 384 + 128 + k] = hh; g_XNL[n * 384 + 128 + k] = ll;
    split1(o2, hh, ll); g_XNH[n * 384 + 256 + k] = hh; g_XNL[n * 384 + 256 + k] = ll;
}

// ---------------- launch ----------------
extern "C" void kernel_launch(void* const* d_in, const int* in_sizes, int n_in,
                              void* d_out, int out_size) {
    const int*   z      = (const int*)d_in[0];
    const float* pos    = (const float*)d_in[1];
    const int*   ei     = (const int*)d_in[3];
    const float* emb_w  = (const float*)d_in[4];
    const float* emb2_w = (const float*)d_in[5];
    const float* emb2_b = (const float*)d_in[6];
    const float* dp1w   = (const float*)d_in[7];
    const float* dp1b   = (const float*)d_in[8];
    const float* dp2w   = (const float*)d_in[9];
    const float* dp2b   = (const float*)d_in[10];
    const float* dp3w   = (const float*)d_in[11];
    const float* dp3b   = (const float*)d_in[12];
    const float* lt0w   = (const float*)d_in[13];
    const float* lt1w   = (const float*)d_in[14];
    const float* lt2w   = (const float*)d_in[15];
    const float* ls0w   = (const float*)d_in[16];
    const float* ls0b   = (const float*)d_in[17];
    const float* ls1w   = (const float*)d_in[18];
    const float* ls1b   = (const float*)d_in[19];
    const float* ing    = (const float*)d_in[20];
    const float* inb    = (const float*)d_in[21];
    const float* linw   = (const float*)d_in[22];
    const float* linb   = (const float*)d_in[23];
    const float* ong    = (const float*)d_in[24];
    const float* onb    = (const float*)d_in[25];
    const float* ol1w   = (const float*)d_in[26];
    const float* ol1b   = (const float*)d_in[27];
    const float* ol2w   = (const float*)d_in[28];
    const float* ol2b   = (const float*)d_in[29];
    float* y = (float*)d_out;

    cudaFuncSetAttribute(tc_mix2, cudaFuncAttributeMaxDynamicSharedMemorySize, TG_SMEM);
    cudaFuncSetAttribute(tg_ls1, cudaFuncAttributeMaxDynamicSharedMemorySize, TG_SMEM);
    cudaFuncSetAttribute(tg_tail, cudaFuncAttributeMaxDynamicSharedMemorySize, TG_SMEM);
    cudaFuncSetAttribute(k_edgedp, cudaFuncAttributeMaxDynamicSharedMemorySize, EDP_SMEM);

    k_count<<<368, 256>>>(ei, pos, emb_w, emb2_w, emb2_b,
                          dp1w, dp1b, dp2w, dp2b, dp3w, dp3b);
    k_scan<<<1, 1024>>>();
    k_scatter<<<NE / 256, 256>>>(ei, pos, z);
    k_edgedp<<<EDP_BLOCKS, 256, EDP_SMEM>>>();
    k_gather<<<NN, 128>>>(z, ing, inb);
    k_wprep<<<928, 256>>>(ls0w, ls1w, linw, lt0w, lt1w, lt2w, ol1w);
    tc_mix2<<<1024, 256, TG_SMEM>>>(ls0b);
    tg_ls1<<<dim3(NN / 128, 3), 256, TG_SMEM>>>(ls1b);
    k_combine_ln<<<NN, 128>>>(ong, onb);
    tg_tail<<<NN / 128, 256, TG_SMEM>>>(linb, ol1b, ol2w, ol2b, y);
}